// round 12
// baseline (speedup 1.0000x reference)
#include <cuda_runtime.h>
#include <cstdint>

#define B_ 4
#define S_ 2048
#define D_ 1024
#define H_ 16
#define DK_ 64
#define M_ (B_ * S_)   // 8192

__device__ float g_q[M_ * D_];     // [B,H,S,DK] tf32, q pre-scaled by 0.125*log2e
__device__ float g_k[M_ * D_];     // [B,H,S,DK] tf32
__device__ float g_vT[M_ * D_];    // [B,H,DK,S] tf32 (V projected + transposed)
__device__ float g_x[M_ * D_];     // [B,S,D] attention out, tf32-rounded
__device__ float g_rq[M_ * D_];
__device__ float g_rk[M_ * D_];
__device__ float g_rv[M_ * D_];
__device__ float g_rwq[D_ * D_];
__device__ float g_rwk[D_ * D_];
__device__ float g_rwv[D_ * D_];
__device__ float g_rwo[D_ * D_];
__device__ int   g_mflag[16 * 32];

__device__ __forceinline__ float to_tf32(float x) {
    float r;
    asm("cvt.rna.tf32.f32 %0, %1;" : "=f"(r) : "f"(x));
    return r;
}

__device__ __forceinline__ void mma8(float c[4], float a0, float a1, float a2, float a3,
                                     float b0, float b1) {
    asm volatile(
        "mma.sync.aligned.m16n8k8.row.col.f32.tf32.tf32.f32 "
        "{%0,%1,%2,%3}, {%4,%5,%6,%7}, {%8,%9}, {%0,%1,%2,%3};"
        : "+f"(c[0]), "+f"(c[1]), "+f"(c[2]), "+f"(c[3])
        : "r"(__float_as_uint(a0)), "r"(__float_as_uint(a1)),
          "r"(__float_as_uint(a2)), "r"(__float_as_uint(a3)),
          "r"(__float_as_uint(b0)), "r"(__float_as_uint(b1)));
}

__device__ __forceinline__ uint32_t smem_u32(const void* p) {
    return (uint32_t)__cvta_generic_to_shared(p);
}
__device__ __forceinline__ void cp_async16(uint32_t dst, const float* src) {
    asm volatile("cp.async.ca.shared.global [%0], [%1], 16;" :: "r"(dst), "l"(src));
}
#define CP_COMMIT() asm volatile("cp.async.commit_group;")
#define CP_WAIT1()  asm volatile("cp.async.wait_group 1;")
#define CP_WAIT0()  asm volatile("cp.async.wait_group 0;")

// ---------------------------------------------------------------------------
// Prepass kernels
// ---------------------------------------------------------------------------
__global__ __launch_bounds__(256) void pre_act_kernel(
    const float* __restrict__ q, const float* __restrict__ k, const float* __restrict__ v)
{
    const int which = blockIdx.y;
    const float* src = (which == 0) ? q : (which == 1) ? k : v;
    float* dst = (which == 0) ? g_rq : (which == 1) ? g_rk : g_rv;
    const int n4 = M_ * D_ / 4;
    const int stride = gridDim.x * blockDim.x;
    for (int i = blockIdx.x * blockDim.x + threadIdx.x; i < n4; i += stride) {
        float4 t = ((const float4*)src)[i];
        ((float4*)dst)[i] =
            make_float4(to_tf32(t.x), to_tf32(t.y), to_tf32(t.z), to_tf32(t.w));
    }
}

__global__ __launch_bounds__(256) void pre_w_kernel(
    const float* __restrict__ wq, const float* __restrict__ wk,
    const float* __restrict__ wv, const float* __restrict__ wo)
{
    const int which = blockIdx.y;
    const float* src = (which == 0) ? wq : (which == 1) ? wk : (which == 2) ? wv : wo;
    float* dst = (which == 0) ? g_rwq : (which == 1) ? g_rwk : (which == 2) ? g_rwv : g_rwo;
    const int n4 = D_ * D_ / 4;
    const int stride = gridDim.x * blockDim.x;
    for (int i = blockIdx.x * blockDim.x + threadIdx.x; i < n4; i += stride) {
        float4 t = ((const float4*)src)[i];
        ((float4*)dst)[i] =
            make_float4(to_tf32(t.x), to_tf32(t.y), to_tf32(t.z), to_tf32(t.w));
    }
}

__global__ __launch_bounds__(256) void pre_mask_kernel(const int* __restrict__ mask)
{
    const int qt = blockIdx.x >> 5, kt = blockIdx.x & 31;
    const int tid = threadIdx.x;
    const int r = tid >> 1, h = tid & 1;
    const int* p = mask + (qt * 128 + r) * S_ + kt * 64 + h * 32;
    bool ok = true;
#pragma unroll
    for (int j = 0; j < 8; j++) {
        int4 mv = *(const int4*)(p + j * 4);
        ok &= (mv.x != 0) & (mv.y != 0) & (mv.z != 0) & (mv.w != 0);
    }
    const int all = __syncthreads_and((int)ok);
    if (tid == 0) g_mflag[qt * 32 + kt] = all;
}

// ---------------------------------------------------------------------------
// tf32 tensor-core GEMM: BM=128, BN=256, BK=32, 3-stage pipeline (wait_group 1
// => prefetch distance 2 iterations, gmem latency hidden), 8 warps as 2m x 4n,
// warp tile 64x64. Stride-40 smem, conflict-free float2 fragments, k-slot
// permutation on A and B (dot preserved).
// MODE 0: out [M,D]; 1: head-split [B,H,S,DK]; 2: split+transposed [B,H,DK,S].
// ---------------------------------------------------------------------------
#define GST 40
#define ASTG (128 * GST)
#define BSTG (256 * GST)
#define GEMM_SMEM_BYTES ((3 * ASTG + 3 * BSTG) * 4)   // 184320 B

template <int MODE>
__device__ __forceinline__ void gemm_tc(
    float* As, float* Bs,
    const float* __restrict__ X, const float* __restrict__ W,
    const float* __restrict__ bias, float* __restrict__ out, float scale)
{
    const int tid = threadIdx.x;
    const int lane = tid & 31, wid = tid >> 5;
    const int g = lane >> 2, tg = lane & 3;
    const int wm = wid >> 2, wn = wid & 3;      // 2m x 4n warps
    const int m0 = blockIdx.y * 128, n0 = blockIdx.x * 256;

    const uint32_t AsU = smem_u32(As), BsU = smem_u32(Bs);
    const int lr = tid >> 1;            // row 0..127
    const int lsg = (tid & 1) * 16;     // col 0 or 16

    const float* xrow = X + (long long)(m0 + lr) * D_ + lsg;
    const float* wrow0 = W + (long long)(n0 + lr) * D_ + lsg;
    const float* wrow1 = W + (long long)(n0 + lr + 128) * D_ + lsg;
    const uint32_t adst = AsU + (uint32_t)(lr * GST + lsg) * 4;
    const uint32_t bdst0 = BsU + (uint32_t)(lr * GST + lsg) * 4;
    const uint32_t bdst1 = bdst0 + (uint32_t)(128 * GST) * 4;

#define G_ISSUE(s, kb)                                        \
    do {                                                      \
        const float* xs = xrow + (kb) * 32;                   \
        const float* w0 = wrow0 + (kb) * 32;                  \
        const float* w1 = wrow1 + (kb) * 32;                  \
        const uint32_t ao = (uint32_t)((s) * ASTG) * 4;       \
        const uint32_t bo = (uint32_t)((s) * BSTG) * 4;       \
        cp_async16(adst + ao,      xs);                       \
        cp_async16(adst + ao + 16, xs + 4);                   \
        cp_async16(adst + ao + 32, xs + 8);                   \
        cp_async16(adst + ao + 48, xs + 12);                  \
        cp_async16(bdst0 + bo,      w0);                      \
        cp_async16(bdst0 + bo + 16, w0 + 4);                  \
        cp_async16(bdst0 + bo + 32, w0 + 8);                  \
        cp_async16(bdst0 + bo + 48, w0 + 12);                 \
        cp_async16(bdst1 + bo,      w1);                      \
        cp_async16(bdst1 + bo + 16, w1 + 4);                  \
        cp_async16(bdst1 + bo + 32, w1 + 8);                  \
        cp_async16(bdst1 + bo + 48, w1 + 12);                 \
    } while (0)

    float acc[4][8][4];
#pragma unroll
    for (int mt = 0; mt < 4; mt++)
#pragma unroll
        for (int nt = 0; nt < 8; nt++)
#pragma unroll
            for (int i = 0; i < 4; i++) acc[mt][nt][i] = 0.0f;

    G_ISSUE(0, 0);
    CP_COMMIT();
    G_ISSUE(1, 1);
    CP_COMMIT();

    for (int it = 0; it < 32; it++) {
        CP_WAIT1();              // stage for `it` complete; `it+1` may be in flight
        __syncthreads();
        if (it < 30) {
            G_ISSUE((it + 2) % 3, it + 2);
            CP_COMMIT();
        }

        const float* Ab = As + (it % 3) * ASTG;
        const float* Bb = Bs + (it % 3) * BSTG;
#pragma unroll
        for (int kk = 0; kk < 4; kk++) {
            const int kc = kk * 8 + tg * 2;   // k cols 2tg,2tg+1 -> slots tg,tg+4
            float2 a0[4], a1[4];
#pragma unroll
            for (int mt = 0; mt < 4; mt++) {
                const int rb = wm * 64 + mt * 16 + g;
                a0[mt] = *(const float2*)&Ab[rb * GST + kc];
                a1[mt] = *(const float2*)&Ab[(rb + 8) * GST + kc];
            }
#pragma unroll
            for (int nt = 0; nt < 8; nt++) {
                const float2 b = *(const float2*)&Bb[(wn * 64 + nt * 8 + g) * GST + kc];
#pragma unroll
                for (int mt = 0; mt < 4; mt++)
                    mma8(acc[mt][nt], a0[mt].x, a1[mt].x, a0[mt].y, a1[mt].y, b.x, b.y);
            }
        }
    }
#undef G_ISSUE

#pragma unroll
    for (int mt = 0; mt < 4; mt++) {
        const int r0 = m0 + wm * 64 + mt * 16 + g;
#pragma unroll
        for (int nt = 0; nt < 8; nt++) {
            const int c = n0 + wn * 64 + nt * 8 + tg * 2;
            const float bv0 = bias[c], bv1 = bias[c + 1];
            float v00 = acc[mt][nt][0] + bv0, v01 = acc[mt][nt][1] + bv1;
            float v10 = acc[mt][nt][2] + bv0, v11 = acc[mt][nt][3] + bv1;
            if (MODE >= 1) {
                v00 = to_tf32(v00 * scale); v01 = to_tf32(v01 * scale);
                v10 = to_tf32(v10 * scale); v11 = to_tf32(v11 * scale);
                const int h = c >> 6, dk = c & 63;
                const int bb = r0 >> 11, ss = r0 & 2047;
                if (MODE == 1) {
                    float* o0 = &out[(((bb * H_ + h) * S_) + ss) * DK_ + dk];
                    *(float2*)o0 = make_float2(v00, v01);
                    *(float2*)(o0 + 8 * DK_) = make_float2(v10, v11);
                } else {
                    float* o0 = &out[(((bb * H_ + h) * DK_) + dk) * S_ + ss];
                    o0[0] = v00;
                    o0[8] = v10;
                    o0[S_] = v01;
                    o0[S_ + 8] = v11;
                }
            } else {
                *(float2*)&out[r0 * D_ + c] = make_float2(v00, v01);
                *(float2*)&out[(r0 + 8) * D_ + c] = make_float2(v10, v11);
            }
        }
    }
}

// 0.125 * log2(e)
#define QSCALE 0.1803368801111204f

__global__ __launch_bounds__(256) void qkv_kernel(
    const float* __restrict__ bq, const float* __restrict__ bk,
    const float* __restrict__ bv)
{
    extern __shared__ __align__(16) float sm[];
    float* As = sm;
    float* Bs = sm + 3 * ASTG;
    if (blockIdx.z == 0)      gemm_tc<1>(As, Bs, g_rq, g_rwq, bq, g_q, QSCALE);
    else if (blockIdx.z == 1) gemm_tc<1>(As, Bs, g_rk, g_rwk, bk, g_k, 1.0f);
    else                      gemm_tc<2>(As, Bs, g_rv, g_rwv, bv, g_vT, 1.0f);
}

__global__ __launch_bounds__(256) void oproj_kernel(
    const float* __restrict__ bo, float* __restrict__ out)
{
    extern __shared__ __align__(16) float sm[];
    float* As = sm;
    float* Bs = sm + 3 * ASTG;
    gemm_tc<0>(As, Bs, g_x, g_rwo, bo, out, 1.0f);
}

// ---------------------------------------------------------------------------
// Flash attention (unchanged): Br=256, Q/P in registers, XOR-swizzled
// stride-64 K/V smem, double-buffered cp.async, base-2 softmax.
// ---------------------------------------------------------------------------
#define ATKV (64 * 64)
#define ATTN_SMEM_BYTES (4 * ATKV * 4)   // 65536 B

__global__ __launch_bounds__(256) void attn_kernel(const int* __restrict__ mask)
{
    extern __shared__ __align__(16) float sm[];
    float* Ks = sm;
    float* Vt = sm + 2 * ATKV;

    const int tid = threadIdx.x;
    const int lane = tid & 31, wid = tid >> 5;
    const int g = lane >> 2, tg = lane & 3;
    const int w32 = wid * 32;
    const int q0 = blockIdx.x * 256;
    const int bh = blockIdx.y;

    const float* Qg = g_q + bh * S_ * DK_;
    const float* Kg = g_k + bh * S_ * DK_;
    const float* Vg = g_vT + bh * DK_ * S_;

    const uint32_t KsU = smem_u32(Ks), VtU = smem_u32(Vt);
    const int r = tid >> 2, qd = tid & 3;
    const int rsw = (r & 7) * 8;

#define KV_ISSUE(s, t)                                                          \
    do {                                                                        \
        const float* ksrc = Kg + ((t) * 64 + r) * DK_ + qd * 16;                \
        const float* vsrc = Vg + r * S_ + (t) * 64 + qd * 16;                   \
        const uint32_t kdb = KsU + (uint32_t)((s) * ATKV + r * 64) * 4;         \
        const uint32_t vdb = VtU + (uint32_t)((s) * ATKV + r * 64) * 4;         \
        _Pragma("unroll")                                                       \
        for (int j = 0; j < 4; j++) {                                           \
            const uint32_t co = (uint32_t)((qd * 16 + j * 4) ^ rsw) * 4;        \
            cp_async16(kdb + co, ksrc + j * 4);                                 \
            cp_async16(vdb + co, vsrc + j * 4);                                 \
        }                                                                       \
    } while (0)

    KV_ISSUE(0, 0);
    CP_COMMIT();
    KV_ISSUE(1, 1);
    CP_COMMIT();

    float2 qA[2][8], qB[2][8];
#pragma unroll
    for (int mt = 0; mt < 2; mt++) {
        const float* qlo = Qg + (q0 + w32 + mt * 16 + g) * DK_ + tg * 2;
        const float* qhi = qlo + 8 * DK_;
#pragma unroll
        for (int kk = 0; kk < 8; kk++) {
            qA[mt][kk] = *(const float2*)(qlo + kk * 8);
            qB[mt][kk] = *(const float2*)(qhi + kk * 8);
        }
    }

    float mr[2][2], lr2[2][2];
#pragma unroll
    for (int mt = 0; mt < 2; mt++) {
        mr[mt][0] = -1e30f; mr[mt][1] = -1e30f;
        lr2[mt][0] = 0.0f;  lr2[mt][1] = 0.0f;
    }
    float o[2][8][4];
#pragma unroll
    for (int mt = 0; mt < 2; mt++)
#pragma unroll
        for (int nt = 0; nt < 8; nt++)
#pragma unroll
            for (int i = 0; i < 4; i++) o[mt][nt][i] = 0.0f;

    const int mrow = blockIdx.x * 2;

    for (int kt = 0; kt < 32; kt++) {
        CP_WAIT1();
        __syncthreads();
        const float* Ksb = Ks + (kt & 1) * ATKV;
        const float* Vtb = Vt + (kt & 1) * ATKV;

        float s[2][8][4];
#pragma unroll
        for (int mt = 0; mt < 2; mt++)
#pragma unroll
            for (int nt = 0; nt < 8; nt++)
#pragma unroll
                for (int i = 0; i < 4; i++) s[mt][nt][i] = 0.0f;

#pragma unroll
        for (int kk = 0; kk < 8; kk++) {
            const int fo = 8 * (kk ^ g) + tg * 2;
#pragma unroll
            for (int nt = 0; nt < 8; nt++) {
                const float2 bv = *(const float2*)&Ksb[(nt * 8 + g) * 64 + fo];
                mma8(s[0][nt], qA[0][kk].x, qB[0][kk].x, qA[0][kk].y, qB[0][kk].y,
                     bv.x, bv.y);
                mma8(s[1][nt], qA[1][kk].x, qB[1][kk].x, qA[1][kk].y, qB[1][kk].y,
                     bv.x, bv.y);
            }
        }

        if (!(g_mflag[mrow * 32 + kt] & g_mflag[(mrow + 1) * 32 + kt])) {
            const int k0 = kt * 64;
#pragma unroll
            for (int mt = 0; mt < 2; mt++) {
                const int* mp0 = mask + (q0 + w32 + mt * 16 + g) * S_ + k0 + tg * 2;
                const int* mp1 = mp0 + 8 * S_;
#pragma unroll
                for (int nt = 0; nt < 8; nt++) {
                    const int2 m0v = *(const int2*)(mp0 + nt * 8);
                    const int2 m1v = *(const int2*)(mp1 + nt * 8);
                    if (m0v.x == 0) s[mt][nt][0] = -1e9f;
                    if (m0v.y == 0) s[mt][nt][1] = -1e9f;
                    if (m1v.x == 0) s[mt][nt][2] = -1e9f;
                    if (m1v.y == 0) s[mt][nt][3] = -1e9f;
                }
            }
        }

#pragma unroll
        for (int mt = 0; mt < 2; mt++) {
            float mx0 = -1e30f, mx1 = -1e30f;
#pragma unroll
            for (int nt = 0; nt < 8; nt++) {
                mx0 = fmaxf(mx0, fmaxf(s[mt][nt][0], s[mt][nt][1]));
                mx1 = fmaxf(mx1, fmaxf(s[mt][nt][2], s[mt][nt][3]));
            }
            mx0 = fmaxf(mx0, __shfl_xor_sync(0xffffffffu, mx0, 1));
            mx0 = fmaxf(mx0, __shfl_xor_sync(0xffffffffu, mx0, 2));
            mx1 = fmaxf(mx1, __shfl_xor_sync(0xffffffffu, mx1, 1));
            mx1 = fmaxf(mx1, __shfl_xor_sync(0xffffffffu, mx1, 2));
            const float mn0 = fmaxf(mr[mt][0], mx0);
            const float mn1 = fmaxf(mr[mt][1], mx1);
            const float al0 = exp2f(mr[mt][0] - mn0);
            const float al1 = exp2f(mr[mt][1] - mn1);
            mr[mt][0] = mn0; mr[mt][1] = mn1;

            float sum0 = 0.0f, sum1 = 0.0f;
#pragma unroll
            for (int nt = 0; nt < 8; nt++) {
                const float p0 = exp2f(s[mt][nt][0] - mn0);
                const float p1 = exp2f(s[mt][nt][1] - mn0);
                const float p2 = exp2f(s[mt][nt][2] - mn1);
                const float p3 = exp2f(s[mt][nt][3] - mn1);
                sum0 += p0 + p1;
                sum1 += p2 + p3;
                s[mt][nt][0] = to_tf32(p0);
                s[mt][nt][1] = to_tf32(p1);
                s[mt][nt][2] = to_tf32(p2);
                s[mt][nt][3] = to_tf32(p3);
                o[mt][nt][0] *= al0; o[mt][nt][1] *= al0;
                o[mt][nt][2] *= al1; o[mt][nt][3] *= al1;
            }
            sum0 += __shfl_xor_sync(0xffffffffu, sum0, 1);
            sum0 += __shfl_xor_sync(0xffffffffu, sum0, 2);
            sum1 += __shfl_xor_sync(0xffffffffu, sum1, 1);
            sum1 += __shfl_xor_sync(0xffffffffu, sum1, 2);
            lr2[mt][0] = lr2[mt][0] * al0 + sum0;
            lr2[mt][1] = lr2[mt][1] * al1 + sum1;
        }

#pragma unroll
        for (int kk = 0; kk < 8; kk++) {
            const int fo = 8 * (kk ^ g) + tg * 2;
#pragma unroll
            for (int nt = 0; nt < 8; nt++) {
                const float2 bv = *(const float2*)&Vtb[(nt * 8 + g) * 64 + fo];
                mma8(o[0][nt], s[0][kk][0], s[0][kk][2], s[0][kk][1], s[0][kk][3],
                     bv.x, bv.y);
                mma8(o[1][nt], s[1][kk][0], s[1][kk][2], s[1][kk][1], s[1][kk][3],
                     bv.x, bv.y);
            }
        }

        __syncthreads();
        KV_ISSUE(kt & 1, (kt + 2) & 31);
        CP_COMMIT();
    }
#undef KV_ISSUE

    CP_WAIT0();

    const int bb = bh >> 4, h = bh & 15;
#pragma unroll
    for (int mt = 0; mt < 2; mt++) {
        const float inv0 = 1.0f / lr2[mt][0];
        const float inv1 = 1.0f / lr2[mt][1];
        const int r0 = q0 + w32 + mt * 16 + g;
        float* O0 = &g_x[(bb * S_ + r0) * D_ + h * DK_ + tg * 2];
        float* O1 = O0 + 8 * D_;
#pragma unroll
        for (int nt = 0; nt < 8; nt++) {
            *(float2*)(O0 + nt * 8) =
                make_float2(to_tf32(o[mt][nt][0] * inv0), to_tf32(o[mt][nt][1] * inv0));
            *(float2*)(O1 + nt * 8) =
                make_float2(to_tf32(o[mt][nt][2] * inv1), to_tf32(o[mt][nt][3] * inv1));
        }
    }
}

// ---------------------------------------------------------------------------
extern "C" void kernel_launch(void* const* d_in, const int* in_sizes, int n_in,
                              void* d_out, int out_size)
{
    (void)in_sizes; (void)n_in; (void)out_size;
    const float* q    = (const float*)d_in[0];
    const float* k    = (const float*)d_in[1];
    const float* v    = (const float*)d_in[2];
    const int*   mask = (const int*)d_in[3];
    const float* wq   = (const float*)d_in[4];
    const float* bq   = (const float*)d_in[5];
    const float* wk   = (const float*)d_in[6];
    const float* bk   = (const float*)d_in[7];
    const float* wv   = (const float*)d_in[8];
    const float* bv   = (const float*)d_in[9];
    const float* wo   = (const float*)d_in[10];
    const float* bo   = (const float*)d_in[11];
    float* out = (float*)d_out;

    static bool attrs_set = false;
    if (!attrs_set) {
        cudaFuncSetAttribute(qkv_kernel, cudaFuncAttributeMaxDynamicSharedMemorySize,
                             GEMM_SMEM_BYTES);
        cudaFuncSetAttribute(oproj_kernel, cudaFuncAttributeMaxDynamicSharedMemorySize,
                             GEMM_SMEM_BYTES);
        cudaFuncSetAttribute(attn_kernel, cudaFuncAttributeMaxDynamicSharedMemorySize,
                             ATTN_SMEM_BYTES);
        attrs_set = true;
    }

    // Prepass (3 launches so qkv is the 4th = ncu capture slot)
    dim3 ga(512, 3);
    pre_act_kernel<<<ga, 256>>>(q, k, v);
    dim3 gw(256, 4);
    pre_w_kernel<<<gw, 256>>>(wq, wk, wv, wo);
    pre_mask_kernel<<<512, 256>>>(mask);

    // QKV projections (BN=256; V writes g_vT directly)
    dim3 gqkv(D_ / 256, M_ / 128, 3);
    qkv_kernel<<<gqkv, 256, GEMM_SMEM_BYTES>>>(bq, bk, bv);

    // Attention
    dim3 gattn(S_ / 256, B_ * H_);
    attn_kernel<<<gattn, 256, ATTN_SMEM_BYTES>>>(mask);

    // Output projection
    dim3 gop(D_ / 256, M_ / 128);
    oproj_kernel<<<gop, 256, GEMM_SMEM_BYTES>>>(bo, out);
}

// round 13
// speedup vs baseline: 1.1415x; 1.1415x over previous
#include <cuda_runtime.h>
#include <cstdint>

#define B_ 4
#define S_ 2048
#define D_ 1024
#define H_ 16
#define DK_ 64
#define M_ (B_ * S_)   // 8192

__device__ float g_q[M_ * D_];     // [B,H,S,DK] tf32, q pre-scaled by 0.125*log2e
__device__ float g_k[M_ * D_];     // [B,H,S,DK] tf32
__device__ float g_vT[M_ * D_];    // [B,H,DK,S] tf32 (V projected + transposed)
__device__ float g_x[M_ * D_];     // [B,S,D] attention out, tf32-rounded
__device__ float g_rq[M_ * D_];
__device__ float g_rk[M_ * D_];
__device__ float g_rv[M_ * D_];
__device__ float g_rwq[D_ * D_];
__device__ float g_rwk[D_ * D_];
__device__ float g_rwv[D_ * D_];
__device__ float g_rwo[D_ * D_];
__device__ int   g_mflag[16 * 32];

__device__ __forceinline__ float to_tf32(float x) {
    float r;
    asm("cvt.rna.tf32.f32 %0, %1;" : "=f"(r) : "f"(x));
    return r;
}

__device__ __forceinline__ void mma8(float c[4], float a0, float a1, float a2, float a3,
                                     float b0, float b1) {
    asm volatile(
        "mma.sync.aligned.m16n8k8.row.col.f32.tf32.tf32.f32 "
        "{%0,%1,%2,%3}, {%4,%5,%6,%7}, {%8,%9}, {%0,%1,%2,%3};"
        : "+f"(c[0]), "+f"(c[1]), "+f"(c[2]), "+f"(c[3])
        : "r"(__float_as_uint(a0)), "r"(__float_as_uint(a1)),
          "r"(__float_as_uint(a2)), "r"(__float_as_uint(a3)),
          "r"(__float_as_uint(b0)), "r"(__float_as_uint(b1)));
}

__device__ __forceinline__ uint32_t smem_u32(const void* p) {
    return (uint32_t)__cvta_generic_to_shared(p);
}
__device__ __forceinline__ void cp_async16(uint32_t dst, const float* src) {
    asm volatile("cp.async.ca.shared.global [%0], [%1], 16;" :: "r"(dst), "l"(src));
}
#define CP_COMMIT() asm volatile("cp.async.commit_group;")
#define CP_WAIT1()  asm volatile("cp.async.wait_group 1;")
#define CP_WAIT0()  asm volatile("cp.async.wait_group 0;")

// ---------------------------------------------------------------------------
// Prepass kernels
// ---------------------------------------------------------------------------
__global__ __launch_bounds__(256) void pre_act_kernel(
    const float* __restrict__ q, const float* __restrict__ k, const float* __restrict__ v)
{
    const int which = blockIdx.y;
    const float* src = (which == 0) ? q : (which == 1) ? k : v;
    float* dst = (which == 0) ? g_rq : (which == 1) ? g_rk : g_rv;
    const int n4 = M_ * D_ / 4;
    const int stride = gridDim.x * blockDim.x;
    for (int i = blockIdx.x * blockDim.x + threadIdx.x; i < n4; i += stride) {
        float4 t = ((const float4*)src)[i];
        ((float4*)dst)[i] =
            make_float4(to_tf32(t.x), to_tf32(t.y), to_tf32(t.z), to_tf32(t.w));
    }
}

__global__ __launch_bounds__(256) void pre_w_kernel(
    const float* __restrict__ wq, const float* __restrict__ wk,
    const float* __restrict__ wv, const float* __restrict__ wo)
{
    const int which = blockIdx.y;
    const float* src = (which == 0) ? wq : (which == 1) ? wk : (which == 2) ? wv : wo;
    float* dst = (which == 0) ? g_rwq : (which == 1) ? g_rwk : (which == 2) ? g_rwv : g_rwo;
    const int n4 = D_ * D_ / 4;
    const int stride = gridDim.x * blockDim.x;
    for (int i = blockIdx.x * blockDim.x + threadIdx.x; i < n4; i += stride) {
        float4 t = ((const float4*)src)[i];
        ((float4*)dst)[i] =
            make_float4(to_tf32(t.x), to_tf32(t.y), to_tf32(t.z), to_tf32(t.w));
    }
}

__global__ __launch_bounds__(256) void pre_mask_kernel(const int* __restrict__ mask)
{
    const int qt = blockIdx.x >> 5, kt = blockIdx.x & 31;
    const int tid = threadIdx.x;
    const int r = tid >> 1, h = tid & 1;
    const int* p = mask + (qt * 128 + r) * S_ + kt * 64 + h * 32;
    bool ok = true;
#pragma unroll
    for (int j = 0; j < 8; j++) {
        int4 mv = *(const int4*)(p + j * 4);
        ok &= (mv.x != 0) & (mv.y != 0) & (mv.z != 0) & (mv.w != 0);
    }
    const int all = __syncthreads_and((int)ok);
    if (tid == 0) g_mflag[qt * 32 + kt] = all;
}

// ---------------------------------------------------------------------------
// tf32 tensor-core GEMM: BM=128, BN=256, BK=32, 2-stage double buffer,
// 8 warps as 2m x 4n, warp tile 64x64, stride-40 smem. COALESCED loader:
// per cp.async instruction a warp covers 4 consecutive rows' 128B chunks
// (4 L1 lines/instr instead of 16 => 4x fewer L1 wavefronts).
// MODE 0: out [M,D]; 1: head-split [B,H,S,DK]; 2: split+transposed [B,H,DK,S].
// ---------------------------------------------------------------------------
#define GST 40
#define ASTG (128 * GST)
#define BSTG (256 * GST)
#define GEMM_SMEM_BYTES ((2 * ASTG + 2 * BSTG) * 4)   // 122880 B

template <int MODE>
__device__ __forceinline__ void gemm_tc(
    float* As, float* Bs,
    const float* __restrict__ X, const float* __restrict__ W,
    const float* __restrict__ bias, float* __restrict__ out, float scale)
{
    const int tid = threadIdx.x;
    const int lane = tid & 31, wid = tid >> 5;
    const int g = lane >> 2, tg = lane & 3;
    const int wm = wid >> 2, wn = wid & 3;      // 2m x 4n warps
    const int m0 = blockIdx.y * 128, n0 = blockIdx.x * 256;

    const uint32_t AsU = smem_u32(As), BsU = smem_u32(Bs);
    const int slot = tid & 7;        // 16B slot within a row's 128B chunk
    const int rgrp = tid >> 3;       // 0..31 (base row; rows rgrp + 32*i)

    const float* xbase = X + (long long)(m0 + rgrp) * D_ + slot * 4;
    const float* wbase = W + (long long)(n0 + rgrp) * D_ + slot * 4;
    const uint32_t adst = AsU + (uint32_t)(rgrp * GST + slot * 4) * 4;
    const uint32_t bdst = BsU + (uint32_t)(rgrp * GST + slot * 4) * 4;
    const uint32_t sstep = (uint32_t)(32 * GST) * 4;   // 32-row smem step

#define G_ISSUE(s, kb)                                                 \
    do {                                                               \
        const uint32_t ao = (uint32_t)((s) * ASTG) * 4;                \
        const uint32_t bo = (uint32_t)((s) * BSTG) * 4;                \
        _Pragma("unroll")                                              \
        for (int i = 0; i < 4; i++)                                    \
            cp_async16(adst + ao + i * sstep,                          \
                       xbase + (long long)i * 32 * D_ + (kb) * 32);    \
        _Pragma("unroll")                                              \
        for (int i = 0; i < 8; i++)                                    \
            cp_async16(bdst + bo + i * sstep,                          \
                       wbase + (long long)i * 32 * D_ + (kb) * 32);    \
    } while (0)

    float acc[4][8][4];
#pragma unroll
    for (int mt = 0; mt < 4; mt++)
#pragma unroll
        for (int nt = 0; nt < 8; nt++)
#pragma unroll
            for (int i = 0; i < 4; i++) acc[mt][nt][i] = 0.0f;

    G_ISSUE(0, 0);
    CP_COMMIT();

    for (int it = 0; it < 32; it++) {
        CP_WAIT0();
        __syncthreads();
        if (it < 31) {
            G_ISSUE((it + 1) & 1, it + 1);
            CP_COMMIT();
        }

        const float* Ab = As + (it & 1) * ASTG;
        const float* Bb = Bs + (it & 1) * BSTG;
#pragma unroll
        for (int kk = 0; kk < 4; kk++) {
            const int kc = kk * 8 + tg * 2;   // k cols 2tg,2tg+1 -> slots tg,tg+4
            float2 a0[4], a1[4];
#pragma unroll
            for (int mt = 0; mt < 4; mt++) {
                const int rb = wm * 64 + mt * 16 + g;
                a0[mt] = *(const float2*)&Ab[rb * GST + kc];
                a1[mt] = *(const float2*)&Ab[(rb + 8) * GST + kc];
            }
#pragma unroll
            for (int nt = 0; nt < 8; nt++) {
                const float2 b = *(const float2*)&Bb[(wn * 64 + nt * 8 + g) * GST + kc];
#pragma unroll
                for (int mt = 0; mt < 4; mt++)
                    mma8(acc[mt][nt], a0[mt].x, a1[mt].x, a0[mt].y, a1[mt].y, b.x, b.y);
            }
        }
    }
#undef G_ISSUE

#pragma unroll
    for (int mt = 0; mt < 4; mt++) {
        const int r0 = m0 + wm * 64 + mt * 16 + g;
#pragma unroll
        for (int nt = 0; nt < 8; nt++) {
            const int c = n0 + wn * 64 + nt * 8 + tg * 2;
            const float bv0 = bias[c], bv1 = bias[c + 1];
            float v00 = acc[mt][nt][0] + bv0, v01 = acc[mt][nt][1] + bv1;
            float v10 = acc[mt][nt][2] + bv0, v11 = acc[mt][nt][3] + bv1;
            if (MODE >= 1) {
                v00 = to_tf32(v00 * scale); v01 = to_tf32(v01 * scale);
                v10 = to_tf32(v10 * scale); v11 = to_tf32(v11 * scale);
                const int h = c >> 6, dk = c & 63;
                const int bb = r0 >> 11, ss = r0 & 2047;
                if (MODE == 1) {
                    float* o0 = &out[(((bb * H_ + h) * S_) + ss) * DK_ + dk];
                    *(float2*)o0 = make_float2(v00, v01);
                    *(float2*)(o0 + 8 * DK_) = make_float2(v10, v11);
                } else {
                    float* o0 = &out[(((bb * H_ + h) * DK_) + dk) * S_ + ss];
                    o0[0] = v00;
                    o0[8] = v10;
                    o0[S_] = v01;
                    o0[S_ + 8] = v11;
                }
            } else {
                *(float2*)&out[r0 * D_ + c] = make_float2(v00, v01);
                *(float2*)&out[(r0 + 8) * D_ + c] = make_float2(v10, v11);
            }
        }
    }
}

// 0.125 * log2(e)
#define QSCALE 0.1803368801111204f

__global__ __launch_bounds__(256) void qkv_kernel(
    const float* __restrict__ bq, const float* __restrict__ bk,
    const float* __restrict__ bv)
{
    extern __shared__ __align__(16) float sm[];
    float* As = sm;
    float* Bs = sm + 2 * ASTG;
    if (blockIdx.z == 0)      gemm_tc<1>(As, Bs, g_rq, g_rwq, bq, g_q, QSCALE);
    else if (blockIdx.z == 1) gemm_tc<1>(As, Bs, g_rk, g_rwk, bk, g_k, 1.0f);
    else                      gemm_tc<2>(As, Bs, g_rv, g_rwv, bv, g_vT, 1.0f);
}

__global__ __launch_bounds__(256) void oproj_kernel(
    const float* __restrict__ bo, float* __restrict__ out)
{
    extern __shared__ __align__(16) float sm[];
    float* As = sm;
    float* Bs = sm + 2 * ASTG;
    gemm_tc<0>(As, Bs, g_x, g_rwo, bo, out, 1.0f);
}

// ---------------------------------------------------------------------------
// Flash attention: Br=256, Q/P in registers, XOR-swizzled stride-64 K/V smem,
// double-buffered cp.async (now coalesced: warp covers 2 consecutive rows'
// 256B chunks per instruction), base-2 softmax.
// ---------------------------------------------------------------------------
#define ATKV (64 * 64)
#define ATTN_SMEM_BYTES (4 * ATKV * 4)   // 65536 B

__global__ __launch_bounds__(256) void attn_kernel(const int* __restrict__ mask)
{
    extern __shared__ __align__(16) float sm[];
    float* Ks = sm;
    float* Vt = sm + 2 * ATKV;

    const int tid = threadIdx.x;
    const int lane = tid & 31, wid = tid >> 5;
    const int g = lane >> 2, tg = lane & 3;
    const int w32 = wid * 32;
    const int q0 = blockIdx.x * 256;
    const int bh = blockIdx.y;

    const float* Qg = g_q + bh * S_ * DK_;
    const float* Kg = g_k + bh * S_ * DK_;
    const float* Vg = g_vT + bh * DK_ * S_;

    const uint32_t KsU = smem_u32(Ks), VtU = smem_u32(Vt);
    const int slot = tid & 15;       // 16B slot within a row's 256B chunk
    const int rg = tid >> 4;         // 0..15 (base row; rows rg + 16*i)

#define KV_ISSUE(s, t)                                                            \
    do {                                                                          \
        const uint32_t so = (uint32_t)((s) * ATKV) * 4;                           \
        _Pragma("unroll")                                                         \
        for (int i = 0; i < 4; i++) {                                             \
            const int row = rg + 16 * i;                                          \
            const uint32_t co = (uint32_t)((slot * 4) ^ ((row & 7) * 8)) * 4;     \
            cp_async16(KsU + so + (uint32_t)(row * 64) * 4 + co,                  \
                       Kg + ((t) * 64 + row) * DK_ + slot * 4);                   \
            cp_async16(VtU + so + (uint32_t)(row * 64) * 4 + co,                  \
                       Vg + row * S_ + (t) * 64 + slot * 4);                      \
        }                                                                         \
    } while (0)

    KV_ISSUE(0, 0);
    CP_COMMIT();
    KV_ISSUE(1, 1);
    CP_COMMIT();

    float2 qA[2][8], qB[2][8];
#pragma unroll
    for (int mt = 0; mt < 2; mt++) {
        const float* qlo = Qg + (q0 + w32 + mt * 16 + g) * DK_ + tg * 2;
        const float* qhi = qlo + 8 * DK_;
#pragma unroll
        for (int kk = 0; kk < 8; kk++) {
            qA[mt][kk] = *(const float2*)(qlo + kk * 8);
            qB[mt][kk] = *(const float2*)(qhi + kk * 8);
        }
    }

    float mr[2][2], lr2[2][2];
#pragma unroll
    for (int mt = 0; mt < 2; mt++) {
        mr[mt][0] = -1e30f; mr[mt][1] = -1e30f;
        lr2[mt][0] = 0.0f;  lr2[mt][1] = 0.0f;
    }
    float o[2][8][4];
#pragma unroll
    for (int mt = 0; mt < 2; mt++)
#pragma unroll
        for (int nt = 0; nt < 8; nt++)
#pragma unroll
            for (int i = 0; i < 4; i++) o[mt][nt][i] = 0.0f;

    const int mrow = blockIdx.x * 2;

    for (int kt = 0; kt < 32; kt++) {
        CP_WAIT1();
        __syncthreads();
        const float* Ksb = Ks + (kt & 1) * ATKV;
        const float* Vtb = Vt + (kt & 1) * ATKV;

        float s[2][8][4];
#pragma unroll
        for (int mt = 0; mt < 2; mt++)
#pragma unroll
            for (int nt = 0; nt < 8; nt++)
#pragma unroll
                for (int i = 0; i < 4; i++) s[mt][nt][i] = 0.0f;

#pragma unroll
        for (int kk = 0; kk < 8; kk++) {
            const int fo = 8 * (kk ^ g) + tg * 2;
#pragma unroll
            for (int nt = 0; nt < 8; nt++) {
                const float2 bv = *(const float2*)&Ksb[(nt * 8 + g) * 64 + fo];
                mma8(s[0][nt], qA[0][kk].x, qB[0][kk].x, qA[0][kk].y, qB[0][kk].y,
                     bv.x, bv.y);
                mma8(s[1][nt], qA[1][kk].x, qB[1][kk].x, qA[1][kk].y, qB[1][kk].y,
                     bv.x, bv.y);
            }
        }

        if (!(g_mflag[mrow * 32 + kt] & g_mflag[(mrow + 1) * 32 + kt])) {
            const int k0 = kt * 64;
#pragma unroll
            for (int mt = 0; mt < 2; mt++) {
                const int* mp0 = mask + (q0 + w32 + mt * 16 + g) * S_ + k0 + tg * 2;
                const int* mp1 = mp0 + 8 * S_;
#pragma unroll
                for (int nt = 0; nt < 8; nt++) {
                    const int2 m0v = *(const int2*)(mp0 + nt * 8);
                    const int2 m1v = *(const int2*)(mp1 + nt * 8);
                    if (m0v.x == 0) s[mt][nt][0] = -1e9f;
                    if (m0v.y == 0) s[mt][nt][1] = -1e9f;
                    if (m1v.x == 0) s[mt][nt][2] = -1e9f;
                    if (m1v.y == 0) s[mt][nt][3] = -1e9f;
                }
            }
        }

#pragma unroll
        for (int mt = 0; mt < 2; mt++) {
            float mx0 = -1e30f, mx1 = -1e30f;
#pragma unroll
            for (int nt = 0; nt < 8; nt++) {
                mx0 = fmaxf(mx0, fmaxf(s[mt][nt][0], s[mt][nt][1]));
                mx1 = fmaxf(mx1, fmaxf(s[mt][nt][2], s[mt][nt][3]));
            }
            mx0 = fmaxf(mx0, __shfl_xor_sync(0xffffffffu, mx0, 1));
            mx0 = fmaxf(mx0, __shfl_xor_sync(0xffffffffu, mx0, 2));
            mx1 = fmaxf(mx1, __shfl_xor_sync(0xffffffffu, mx1, 1));
            mx1 = fmaxf(mx1, __shfl_xor_sync(0xffffffffu, mx1, 2));
            const float mn0 = fmaxf(mr[mt][0], mx0);
            const float mn1 = fmaxf(mr[mt][1], mx1);
            const float al0 = exp2f(mr[mt][0] - mn0);
            const float al1 = exp2f(mr[mt][1] - mn1);
            mr[mt][0] = mn0; mr[mt][1] = mn1;

            float sum0 = 0.0f, sum1 = 0.0f;
#pragma unroll
            for (int nt = 0; nt < 8; nt++) {
                const float p0 = exp2f(s[mt][nt][0] - mn0);
                const float p1 = exp2f(s[mt][nt][1] - mn0);
                const float p2 = exp2f(s[mt][nt][2] - mn1);
                const float p3 = exp2f(s[mt][nt][3] - mn1);
                sum0 += p0 + p1;
                sum1 += p2 + p3;
                s[mt][nt][0] = to_tf32(p0);
                s[mt][nt][1] = to_tf32(p1);
                s[mt][nt][2] = to_tf32(p2);
                s[mt][nt][3] = to_tf32(p3);
                o[mt][nt][0] *= al0; o[mt][nt][1] *= al0;
                o[mt][nt][2] *= al1; o[mt][nt][3] *= al1;
            }
            sum0 += __shfl_xor_sync(0xffffffffu, sum0, 1);
            sum0 += __shfl_xor_sync(0xffffffffu, sum0, 2);
            sum1 += __shfl_xor_sync(0xffffffffu, sum1, 1);
            sum1 += __shfl_xor_sync(0xffffffffu, sum1, 2);
            lr2[mt][0] = lr2[mt][0] * al0 + sum0;
            lr2[mt][1] = lr2[mt][1] * al1 + sum1;
        }

#pragma unroll
        for (int kk = 0; kk < 8; kk++) {
            const int fo = 8 * (kk ^ g) + tg * 2;
#pragma unroll
            for (int nt = 0; nt < 8; nt++) {
                const float2 bv = *(const float2*)&Vtb[(nt * 8 + g) * 64 + fo];
                mma8(o[0][nt], s[0][kk][0], s[0][kk][2], s[0][kk][1], s[0][kk][3],
                     bv.x, bv.y);
                mma8(o[1][nt], s[1][kk][0], s[1][kk][2], s[1][kk][1], s[1][kk][3],
                     bv.x, bv.y);
            }
        }

        __syncthreads();
        KV_ISSUE(kt & 1, (kt + 2) & 31);
        CP_COMMIT();
    }
#undef KV_ISSUE

    CP_WAIT0();

    const int bb = bh >> 4, h = bh & 15;
#pragma unroll
    for (int mt = 0; mt < 2; mt++) {
        const float inv0 = 1.0f / lr2[mt][0];
        const float inv1 = 1.0f / lr2[mt][1];
        const int r0 = q0 + w32 + mt * 16 + g;
        float* O0 = &g_x[(bb * S_ + r0) * D_ + h * DK_ + tg * 2];
        float* O1 = O0 + 8 * D_;
#pragma unroll
        for (int nt = 0; nt < 8; nt++) {
            *(float2*)(O0 + nt * 8) =
                make_float2(to_tf32(o[mt][nt][0] * inv0), to_tf32(o[mt][nt][1] * inv0));
            *(float2*)(O1 + nt * 8) =
                make_float2(to_tf32(o[mt][nt][2] * inv1), to_tf32(o[mt][nt][3] * inv1));
        }
    }
}

// ---------------------------------------------------------------------------
extern "C" void kernel_launch(void* const* d_in, const int* in_sizes, int n_in,
                              void* d_out, int out_size)
{
    (void)in_sizes; (void)n_in; (void)out_size;
    const float* q    = (const float*)d_in[0];
    const float* k    = (const float*)d_in[1];
    const float* v    = (const float*)d_in[2];
    const int*   mask = (const int*)d_in[3];
    const float* wq   = (const float*)d_in[4];
    const float* bq   = (const float*)d_in[5];
    const float* wk   = (const float*)d_in[6];
    const float* bk   = (const float*)d_in[7];
    const float* wv   = (const float*)d_in[8];
    const float* bv   = (const float*)d_in[9];
    const float* wo   = (const float*)d_in[10];
    const float* bo   = (const float*)d_in[11];
    float* out = (float*)d_out;

    static bool attrs_set = false;
    if (!attrs_set) {
        cudaFuncSetAttribute(qkv_kernel, cudaFuncAttributeMaxDynamicSharedMemorySize,
                             GEMM_SMEM_BYTES);
        cudaFuncSetAttribute(oproj_kernel, cudaFuncAttributeMaxDynamicSharedMemorySize,
                             GEMM_SMEM_BYTES);
        cudaFuncSetAttribute(attn_kernel, cudaFuncAttributeMaxDynamicSharedMemorySize,
                             ATTN_SMEM_BYTES);
        attrs_set = true;
    }

    // Prepass (3 launches so qkv is the 4th = ncu capture slot)
    dim3 ga(512, 3);
    pre_act_kernel<<<ga, 256>>>(q, k, v);
    dim3 gw(256, 4);
    pre_w_kernel<<<gw, 256>>>(wq, wk, wv, wo);
    pre_mask_kernel<<<512, 256>>>(mask);

    // QKV projections (BN=256; V writes g_vT directly)
    dim3 gqkv(D_ / 256, M_ / 128, 3);
    qkv_kernel<<<gqkv, 256, GEMM_SMEM_BYTES>>>(bq, bk, bv);

    // Attention
    dim3 gattn(S_ / 256, B_ * H_);
    attn_kernel<<<gattn, 256, ATTN_SMEM_BYTES>>>(mask);

    // Output projection
    dim3 gop(D_ / 256, M_ / 128);
    oproj_kernel<<<gop, 256, GEMM_SMEM_BYTES>>>(bo, out);
}

// round 14
// speedup vs baseline: 1.1518x; 1.0090x over previous
#include <cuda_runtime.h>
#include <cstdint>

#define B_ 4
#define S_ 2048
#define D_ 1024
#define H_ 16
#define DK_ 64
#define M_ (B_ * S_)   // 8192

__device__ float g_q[M_ * D_];     // [B,H,S,DK] tf32, q pre-scaled by 0.125*log2e
__device__ float g_k[M_ * D_];     // [B,H,S,DK] tf32
__device__ float g_vT[M_ * D_];    // [B,H,DK,S] tf32 (V projected + transposed)
__device__ float g_x[M_ * D_];     // [B,S,D] attention out, tf32-rounded
__device__ float g_rq[M_ * D_];
__device__ float g_rk[M_ * D_];
__device__ float g_rv[M_ * D_];
__device__ float g_rwq[D_ * D_];
__device__ float g_rwk[D_ * D_];
__device__ float g_rwv[D_ * D_];
__device__ float g_rwo[D_ * D_];
__device__ int   g_mflag[16 * 32];

__device__ __forceinline__ float to_tf32(float x) {
    float r;
    asm("cvt.rna.tf32.f32 %0, %1;" : "=f"(r) : "f"(x));
    return r;
}

__device__ __forceinline__ void mma8(float c[4], float a0, float a1, float a2, float a3,
                                     float b0, float b1) {
    asm volatile(
        "mma.sync.aligned.m16n8k8.row.col.f32.tf32.tf32.f32 "
        "{%0,%1,%2,%3}, {%4,%5,%6,%7}, {%8,%9}, {%0,%1,%2,%3};"
        : "+f"(c[0]), "+f"(c[1]), "+f"(c[2]), "+f"(c[3])
        : "r"(__float_as_uint(a0)), "r"(__float_as_uint(a1)),
          "r"(__float_as_uint(a2)), "r"(__float_as_uint(a3)),
          "r"(__float_as_uint(b0)), "r"(__float_as_uint(b1)));
}

__device__ __forceinline__ uint32_t smem_u32(const void* p) {
    return (uint32_t)__cvta_generic_to_shared(p);
}
__device__ __forceinline__ void cp_async16(uint32_t dst, const float* src) {
    asm volatile("cp.async.ca.shared.global [%0], [%1], 16;" :: "r"(dst), "l"(src));
}
#define CP_COMMIT() asm volatile("cp.async.commit_group;")
#define CP_WAIT1()  asm volatile("cp.async.wait_group 1;")
#define CP_WAIT0()  asm volatile("cp.async.wait_group 0;")

// ---------------------------------------------------------------------------
// Prepass kernels
// ---------------------------------------------------------------------------
__global__ __launch_bounds__(256) void pre_act_kernel(
    const float* __restrict__ q, const float* __restrict__ k, const float* __restrict__ v)
{
    const int which = blockIdx.y;
    const float* src = (which == 0) ? q : (which == 1) ? k : v;
    float* dst = (which == 0) ? g_rq : (which == 1) ? g_rk : g_rv;
    const int n4 = M_ * D_ / 4;
    const int stride = gridDim.x * blockDim.x;
    for (int i = blockIdx.x * blockDim.x + threadIdx.x; i < n4; i += stride) {
        float4 t = ((const float4*)src)[i];
        ((float4*)dst)[i] =
            make_float4(to_tf32(t.x), to_tf32(t.y), to_tf32(t.z), to_tf32(t.w));
    }
}

__global__ __launch_bounds__(256) void pre_w_kernel(
    const float* __restrict__ wq, const float* __restrict__ wk,
    const float* __restrict__ wv, const float* __restrict__ wo)
{
    const int which = blockIdx.y;
    const float* src = (which == 0) ? wq : (which == 1) ? wk : (which == 2) ? wv : wo;
    float* dst = (which == 0) ? g_rwq : (which == 1) ? g_rwk : (which == 2) ? g_rwv : g_rwo;
    const int n4 = D_ * D_ / 4;
    const int stride = gridDim.x * blockDim.x;
    for (int i = blockIdx.x * blockDim.x + threadIdx.x; i < n4; i += stride) {
        float4 t = ((const float4*)src)[i];
        ((float4*)dst)[i] =
            make_float4(to_tf32(t.x), to_tf32(t.y), to_tf32(t.z), to_tf32(t.w));
    }
}

__global__ __launch_bounds__(256) void pre_mask_kernel(const int* __restrict__ mask)
{
    const int qt = blockIdx.x >> 5, kt = blockIdx.x & 31;
    const int tid = threadIdx.x;
    const int r = tid >> 1, h = tid & 1;
    const int* p = mask + (qt * 128 + r) * S_ + kt * 64 + h * 32;
    bool ok = true;
#pragma unroll
    for (int j = 0; j < 8; j++) {
        int4 mv = *(const int4*)(p + j * 4);
        ok &= (mv.x != 0) & (mv.y != 0) & (mv.z != 0) & (mv.w != 0);
    }
    const int all = __syncthreads_and((int)ok);
    if (tid == 0) g_mflag[qt * 32 + kt] = all;
}

// ---------------------------------------------------------------------------
// tf32 tensor-core GEMM: BM=128, BN=256, BK=32, 2-stage double buffer,
// 8 warps as 2m x 4n, warp tile 64x64. GST=48 smem stride => adjacent rows
// 16 banks apart => LDS.128 fragment loads conflict-free. Each float4 covers
// TWO mma k-steps (slot tg <- col 4tg, slot tg+4 <- col 4tg+1, then z/w),
// same bijection on A and B => dot preserved. Coalesced cp.async loader.
// MODE 0: out [M,D]; 1: head-split [B,H,S,DK]; 2: split+transposed [B,H,DK,S].
// ---------------------------------------------------------------------------
#define GST 48
#define ASTG (128 * GST)
#define BSTG (256 * GST)
#define GEMM_SMEM_BYTES ((2 * ASTG + 2 * BSTG) * 4)   // 147456 B

template <int MODE>
__device__ __forceinline__ void gemm_tc(
    float* As, float* Bs,
    const float* __restrict__ X, const float* __restrict__ W,
    const float* __restrict__ bias, float* __restrict__ out, float scale)
{
    const int tid = threadIdx.x;
    const int lane = tid & 31, wid = tid >> 5;
    const int g = lane >> 2, tg = lane & 3;
    const int wm = wid >> 2, wn = wid & 3;      // 2m x 4n warps
    const int m0 = blockIdx.y * 128, n0 = blockIdx.x * 256;

    const uint32_t AsU = smem_u32(As), BsU = smem_u32(Bs);
    const int slot = tid & 7;        // 16B slot within a row's 128B chunk
    const int rgrp = tid >> 3;       // 0..31 (base row; rows rgrp + 32*i)

    const float* xbase = X + (long long)(m0 + rgrp) * D_ + slot * 4;
    const float* wbase = W + (long long)(n0 + rgrp) * D_ + slot * 4;
    const uint32_t adst = AsU + (uint32_t)(rgrp * GST + slot * 4) * 4;
    const uint32_t bdst = BsU + (uint32_t)(rgrp * GST + slot * 4) * 4;
    const uint32_t sstep = (uint32_t)(32 * GST) * 4;   // 32-row smem step

#define G_ISSUE(s, kb)                                                 \
    do {                                                               \
        const uint32_t ao = (uint32_t)((s) * ASTG) * 4;                \
        const uint32_t bo = (uint32_t)((s) * BSTG) * 4;                \
        _Pragma("unroll")                                              \
        for (int i = 0; i < 4; i++)                                    \
            cp_async16(adst + ao + i * sstep,                          \
                       xbase + (long long)i * 32 * D_ + (kb) * 32);    \
        _Pragma("unroll")                                              \
        for (int i = 0; i < 8; i++)                                    \
            cp_async16(bdst + bo + i * sstep,                          \
                       wbase + (long long)i * 32 * D_ + (kb) * 32);    \
    } while (0)

    float acc[4][8][4];
#pragma unroll
    for (int mt = 0; mt < 4; mt++)
#pragma unroll
        for (int nt = 0; nt < 8; nt++)
#pragma unroll
            for (int i = 0; i < 4; i++) acc[mt][nt][i] = 0.0f;

    G_ISSUE(0, 0);
    CP_COMMIT();

    for (int it = 0; it < 32; it++) {
        CP_WAIT0();
        __syncthreads();
        if (it < 31) {
            G_ISSUE((it + 1) & 1, it + 1);
            CP_COMMIT();
        }

        const float* Ab = As + (it & 1) * ASTG;
        const float* Bb = Bs + (it & 1) * BSTG;
#pragma unroll
        for (int kk2 = 0; kk2 < 2; kk2++) {
            const int kc = kk2 * 16 + tg * 4;   // float4 = cols 4tg..4tg+3
            float4 a0[4], a1[4];
#pragma unroll
            for (int mt = 0; mt < 4; mt++) {
                const int rb = wm * 64 + mt * 16 + g;
                a0[mt] = *(const float4*)&Ab[rb * GST + kc];
                a1[mt] = *(const float4*)&Ab[(rb + 8) * GST + kc];
            }
#pragma unroll
            for (int nt = 0; nt < 8; nt++) {
                const float4 b = *(const float4*)&Bb[(wn * 64 + nt * 8 + g) * GST + kc];
#pragma unroll
                for (int mt = 0; mt < 4; mt++) {
                    mma8(acc[mt][nt], a0[mt].x, a1[mt].x, a0[mt].y, a1[mt].y, b.x, b.y);
                    mma8(acc[mt][nt], a0[mt].z, a1[mt].z, a0[mt].w, a1[mt].w, b.z, b.w);
                }
            }
        }
    }
#undef G_ISSUE

#pragma unroll
    for (int mt = 0; mt < 4; mt++) {
        const int r0 = m0 + wm * 64 + mt * 16 + g;
#pragma unroll
        for (int nt = 0; nt < 8; nt++) {
            const int c = n0 + wn * 64 + nt * 8 + tg * 2;
            const float bv0 = bias[c], bv1 = bias[c + 1];
            float v00 = acc[mt][nt][0] + bv0, v01 = acc[mt][nt][1] + bv1;
            float v10 = acc[mt][nt][2] + bv0, v11 = acc[mt][nt][3] + bv1;
            if (MODE >= 1) {
                v00 = to_tf32(v00 * scale); v01 = to_tf32(v01 * scale);
                v10 = to_tf32(v10 * scale); v11 = to_tf32(v11 * scale);
                const int h = c >> 6, dk = c & 63;
                const int bb = r0 >> 11, ss = r0 & 2047;
                if (MODE == 1) {
                    float* o0 = &out[(((bb * H_ + h) * S_) + ss) * DK_ + dk];
                    *(float2*)o0 = make_float2(v00, v01);
                    *(float2*)(o0 + 8 * DK_) = make_float2(v10, v11);
                } else {
                    float* o0 = &out[(((bb * H_ + h) * DK_) + dk) * S_ + ss];
                    o0[0] = v00;
                    o0[8] = v10;
                    o0[S_] = v01;
                    o0[S_ + 8] = v11;
                }
            } else {
                *(float2*)&out[r0 * D_ + c] = make_float2(v00, v01);
                *(float2*)&out[(r0 + 8) * D_ + c] = make_float2(v10, v11);
            }
        }
    }
}

// 0.125 * log2(e)
#define QSCALE 0.1803368801111204f

__global__ __launch_bounds__(256) void qkv_kernel(
    const float* __restrict__ bq, const float* __restrict__ bk,
    const float* __restrict__ bv)
{
    extern __shared__ __align__(16) float sm[];
    float* As = sm;
    float* Bs = sm + 2 * ASTG;
    if (blockIdx.z == 0)      gemm_tc<1>(As, Bs, g_rq, g_rwq, bq, g_q, QSCALE);
    else if (blockIdx.z == 1) gemm_tc<1>(As, Bs, g_rk, g_rwk, bk, g_k, 1.0f);
    else                      gemm_tc<2>(As, Bs, g_rv, g_rwv, bv, g_vT, 1.0f);
}

__global__ __launch_bounds__(256) void oproj_kernel(
    const float* __restrict__ bo, float* __restrict__ out)
{
    extern __shared__ __align__(16) float sm[];
    float* As = sm;
    float* Bs = sm + 2 * ASTG;
    gemm_tc<0>(As, Bs, g_x, g_rwo, bo, out, 1.0f);
}

// ---------------------------------------------------------------------------
// Flash attention: Br=256, Q/P in registers, XOR-swizzled stride-64 K/V smem,
// coalesced double-buffered cp.async, base-2 softmax, warp-uniform rescale
// skip (bit-identical: multiply-by-1.0 is exact).
// ---------------------------------------------------------------------------
#define ATKV (64 * 64)
#define ATTN_SMEM_BYTES (4 * ATKV * 4)   // 65536 B

__global__ __launch_bounds__(256) void attn_kernel(const int* __restrict__ mask)
{
    extern __shared__ __align__(16) float sm[];
    float* Ks = sm;
    float* Vt = sm + 2 * ATKV;

    const int tid = threadIdx.x;
    const int lane = tid & 31, wid = tid >> 5;
    const int g = lane >> 2, tg = lane & 3;
    const int w32 = wid * 32;
    const int q0 = blockIdx.x * 256;
    const int bh = blockIdx.y;

    const float* Qg = g_q + bh * S_ * DK_;
    const float* Kg = g_k + bh * S_ * DK_;
    const float* Vg = g_vT + bh * DK_ * S_;

    const uint32_t KsU = smem_u32(Ks), VtU = smem_u32(Vt);
    const int slot = tid & 15;       // 16B slot within a row's 256B chunk
    const int rg = tid >> 4;         // 0..15 (base row; rows rg + 16*i)

#define KV_ISSUE(s, t)                                                            \
    do {                                                                          \
        const uint32_t so = (uint32_t)((s) * ATKV) * 4;                           \
        _Pragma("unroll")                                                         \
        for (int i = 0; i < 4; i++) {                                             \
            const int row = rg + 16 * i;                                          \
            const uint32_t co = (uint32_t)((slot * 4) ^ ((row & 7) * 8)) * 4;     \
            cp_async16(KsU + so + (uint32_t)(row * 64) * 4 + co,                  \
                       Kg + ((t) * 64 + row) * DK_ + slot * 4);                   \
            cp_async16(VtU + so + (uint32_t)(row * 64) * 4 + co,                  \
                       Vg + row * S_ + (t) * 64 + slot * 4);                      \
        }                                                                         \
    } while (0)

    KV_ISSUE(0, 0);
    CP_COMMIT();
    KV_ISSUE(1, 1);
    CP_COMMIT();

    float2 qA[2][8], qB[2][8];
#pragma unroll
    for (int mt = 0; mt < 2; mt++) {
        const float* qlo = Qg + (q0 + w32 + mt * 16 + g) * DK_ + tg * 2;
        const float* qhi = qlo + 8 * DK_;
#pragma unroll
        for (int kk = 0; kk < 8; kk++) {
            qA[mt][kk] = *(const float2*)(qlo + kk * 8);
            qB[mt][kk] = *(const float2*)(qhi + kk * 8);
        }
    }

    float mr[2][2], lr2[2][2];
#pragma unroll
    for (int mt = 0; mt < 2; mt++) {
        mr[mt][0] = -1e30f; mr[mt][1] = -1e30f;
        lr2[mt][0] = 0.0f;  lr2[mt][1] = 0.0f;
    }
    float o[2][8][4];
#pragma unroll
    for (int mt = 0; mt < 2; mt++)
#pragma unroll
        for (int nt = 0; nt < 8; nt++)
#pragma unroll
            for (int i = 0; i < 4; i++) o[mt][nt][i] = 0.0f;

    const int mrow = blockIdx.x * 2;

    for (int kt = 0; kt < 32; kt++) {
        CP_WAIT1();
        __syncthreads();
        const float* Ksb = Ks + (kt & 1) * ATKV;
        const float* Vtb = Vt + (kt & 1) * ATKV;

        float s[2][8][4];
#pragma unroll
        for (int mt = 0; mt < 2; mt++)
#pragma unroll
            for (int nt = 0; nt < 8; nt++)
#pragma unroll
                for (int i = 0; i < 4; i++) s[mt][nt][i] = 0.0f;

#pragma unroll
        for (int kk = 0; kk < 8; kk++) {
            const int fo = 8 * (kk ^ g) + tg * 2;
#pragma unroll
            for (int nt = 0; nt < 8; nt++) {
                const float2 bv = *(const float2*)&Ksb[(nt * 8 + g) * 64 + fo];
                mma8(s[0][nt], qA[0][kk].x, qB[0][kk].x, qA[0][kk].y, qB[0][kk].y,
                     bv.x, bv.y);
                mma8(s[1][nt], qA[1][kk].x, qB[1][kk].x, qA[1][kk].y, qB[1][kk].y,
                     bv.x, bv.y);
            }
        }

        if (!(g_mflag[mrow * 32 + kt] & g_mflag[(mrow + 1) * 32 + kt])) {
            const int k0 = kt * 64;
#pragma unroll
            for (int mt = 0; mt < 2; mt++) {
                const int* mp0 = mask + (q0 + w32 + mt * 16 + g) * S_ + k0 + tg * 2;
                const int* mp1 = mp0 + 8 * S_;
#pragma unroll
                for (int nt = 0; nt < 8; nt++) {
                    const int2 m0v = *(const int2*)(mp0 + nt * 8);
                    const int2 m1v = *(const int2*)(mp1 + nt * 8);
                    if (m0v.x == 0) s[mt][nt][0] = -1e9f;
                    if (m0v.y == 0) s[mt][nt][1] = -1e9f;
                    if (m1v.x == 0) s[mt][nt][2] = -1e9f;
                    if (m1v.y == 0) s[mt][nt][3] = -1e9f;
                }
            }
        }

#pragma unroll
        for (int mt = 0; mt < 2; mt++) {
            float mx0 = -1e30f, mx1 = -1e30f;
#pragma unroll
            for (int nt = 0; nt < 8; nt++) {
                mx0 = fmaxf(mx0, fmaxf(s[mt][nt][0], s[mt][nt][1]));
                mx1 = fmaxf(mx1, fmaxf(s[mt][nt][2], s[mt][nt][3]));
            }
            mx0 = fmaxf(mx0, __shfl_xor_sync(0xffffffffu, mx0, 1));
            mx0 = fmaxf(mx0, __shfl_xor_sync(0xffffffffu, mx0, 2));
            mx1 = fmaxf(mx1, __shfl_xor_sync(0xffffffffu, mx1, 1));
            mx1 = fmaxf(mx1, __shfl_xor_sync(0xffffffffu, mx1, 2));
            const float mn0 = fmaxf(mr[mt][0], mx0);
            const float mn1 = fmaxf(mr[mt][1], mx1);
            const float al0 = exp2f(mr[mt][0] - mn0);
            const float al1 = exp2f(mr[mt][1] - mn1);
            mr[mt][0] = mn0; mr[mt][1] = mn1;

            float sum0 = 0.0f, sum1 = 0.0f;
#pragma unroll
            for (int nt = 0; nt < 8; nt++) {
                const float p0 = exp2f(s[mt][nt][0] - mn0);
                const float p1 = exp2f(s[mt][nt][1] - mn0);
                const float p2 = exp2f(s[mt][nt][2] - mn1);
                const float p3 = exp2f(s[mt][nt][3] - mn1);
                sum0 += p0 + p1;
                sum1 += p2 + p3;
                s[mt][nt][0] = to_tf32(p0);
                s[mt][nt][1] = to_tf32(p1);
                s[mt][nt][2] = to_tf32(p2);
                s[mt][nt][3] = to_tf32(p3);
            }
            // Rescale O only if any lane's factor != 1.0 (bit-identical skip)
            if (__any_sync(0xffffffffu, (al0 != 1.0f) || (al1 != 1.0f))) {
#pragma unroll
                for (int nt = 0; nt < 8; nt++) {
                    o[mt][nt][0] *= al0; o[mt][nt][1] *= al0;
                    o[mt][nt][2] *= al1; o[mt][nt][3] *= al1;
                }
            }
            sum0 += __shfl_xor_sync(0xffffffffu, sum0, 1);
            sum0 += __shfl_xor_sync(0xffffffffu, sum0, 2);
            sum1 += __shfl_xor_sync(0xffffffffu, sum1, 1);
            sum1 += __shfl_xor_sync(0xffffffffu, sum1, 2);
            lr2[mt][0] = lr2[mt][0] * al0 + sum0;
            lr2[mt][1] = lr2[mt][1] * al1 + sum1;
        }

#pragma unroll
        for (int kk = 0; kk < 8; kk++) {
            const int fo = 8 * (kk ^ g) + tg * 2;
#pragma unroll
            for (int nt = 0; nt < 8; nt++) {
                const float2 bv = *(const float2*)&Vtb[(nt * 8 + g) * 64 + fo];
                mma8(o[0][nt], s[0][kk][0], s[0][kk][2], s[0][kk][1], s[0][kk][3],
                     bv.x, bv.y);
                mma8(o[1][nt], s[1][kk][0], s[1][kk][2], s[1][kk][1], s[1][kk][3],
                     bv.x, bv.y);
            }
        }

        __syncthreads();
        KV_ISSUE(kt & 1, (kt + 2) & 31);
        CP_COMMIT();
    }
#undef KV_ISSUE

    CP_WAIT0();

    const int bb = bh >> 4, h = bh & 15;
#pragma unroll
    for (int mt = 0; mt < 2; mt++) {
        const float inv0 = 1.0f / lr2[mt][0];
        const float inv1 = 1.0f / lr2[mt][1];
        const int r0 = q0 + w32 + mt * 16 + g;
        float* O0 = &g_x[(bb * S_ + r0) * D_ + h * DK_ + tg * 2];
        float* O1 = O0 + 8 * D_;
#pragma unroll
        for (int nt = 0; nt < 8; nt++) {
            *(float2*)(O0 + nt * 8) =
                make_float2(to_tf32(o[mt][nt][0] * inv0), to_tf32(o[mt][nt][1] * inv0));
            *(float2*)(O1 + nt * 8) =
                make_float2(to_tf32(o[mt][nt][2] * inv1), to_tf32(o[mt][nt][3] * inv1));
        }
    }
}

// ---------------------------------------------------------------------------
extern "C" void kernel_launch(void* const* d_in, const int* in_sizes, int n_in,
                              void* d_out, int out_size)
{
    (void)in_sizes; (void)n_in; (void)out_size;
    const float* q    = (const float*)d_in[0];
    const float* k    = (const float*)d_in[1];
    const float* v    = (const float*)d_in[2];
    const int*   mask = (const int*)d_in[3];
    const float* wq   = (const float*)d_in[4];
    const float* bq   = (const float*)d_in[5];
    const float* wk   = (const float*)d_in[6];
    const float* bk   = (const float*)d_in[7];
    const float* wv   = (const float*)d_in[8];
    const float* bv   = (const float*)d_in[9];
    const float* wo   = (const float*)d_in[10];
    const float* bo   = (const float*)d_in[11];
    float* out = (float*)d_out;

    static bool attrs_set = false;
    if (!attrs_set) {
        cudaFuncSetAttribute(qkv_kernel, cudaFuncAttributeMaxDynamicSharedMemorySize,
                             GEMM_SMEM_BYTES);
        cudaFuncSetAttribute(oproj_kernel, cudaFuncAttributeMaxDynamicSharedMemorySize,
                             GEMM_SMEM_BYTES);
        cudaFuncSetAttribute(attn_kernel, cudaFuncAttributeMaxDynamicSharedMemorySize,
                             ATTN_SMEM_BYTES);
        attrs_set = true;
    }

    // Prepass (3 launches so qkv is the 4th = ncu capture slot)
    dim3 ga(512, 3);
    pre_act_kernel<<<ga, 256>>>(q, k, v);
    dim3 gw(256, 4);
    pre_w_kernel<<<gw, 256>>>(wq, wk, wv, wo);
    pre_mask_kernel<<<512, 256>>>(mask);

    // QKV projections (BN=256; V writes g_vT directly)
    dim3 gqkv(D_ / 256, M_ / 128, 3);
    qkv_kernel<<<gqkv, 256, GEMM_SMEM_BYTES>>>(bq, bk, bv);

    // Attention
    dim3 gattn(S_ / 256, B_ * H_);
    attn_kernel<<<gattn, 256, ATTN_SMEM_BYTES>>>(mask);

    // Output projection
    dim3 gop(D_ / 256, M_ / 128);
    oproj_kernel<<<gop, 256, GEMM_SMEM_BYTES>>>(bo, out);
}

// round 15
// speedup vs baseline: 1.4600x; 1.2675x over previous
#include <cuda_runtime.h>
#include <cuda_fp16.h>
#include <cstdint>

#define B_ 4
#define S_ 2048
#define D_ 1024
#define H_ 16
#define DK_ 64
#define M_ (B_ * S_)   // 8192

// fp32 tensors consumed by the (tf32) attention kernel
__device__ float g_q[M_ * D_];     // [B,H,S,DK] tf32, q pre-scaled by 0.125*log2e
__device__ float g_k[M_ * D_];     // [B,H,S,DK] tf32
__device__ float g_vT[M_ * D_];    // [B,H,DK,S] tf32
// fp16 tensors consumed by the GEMMs
__device__ __half g_hq[M_ * D_];
__device__ __half g_hk[M_ * D_];
__device__ __half g_hv[M_ * D_];
__device__ __half g_hwq[D_ * D_];
__device__ __half g_hwk[D_ * D_];
__device__ __half g_hwv[D_ * D_];
__device__ __half g_hwo[D_ * D_];
__device__ __half g_xh[M_ * D_];   // attention out (fp16, oproj input)
__device__ int    g_mflag[16 * 32];

__device__ __forceinline__ float to_tf32(float x) {
    float r;
    asm("cvt.rna.tf32.f32 %0, %1;" : "=f"(r) : "f"(x));
    return r;
}

// tf32 k8 mma (attention)
__device__ __forceinline__ void mma8(float c[4], float a0, float a1, float a2, float a3,
                                     float b0, float b1) {
    asm volatile(
        "mma.sync.aligned.m16n8k8.row.col.f32.tf32.tf32.f32 "
        "{%0,%1,%2,%3}, {%4,%5,%6,%7}, {%8,%9}, {%0,%1,%2,%3};"
        : "+f"(c[0]), "+f"(c[1]), "+f"(c[2]), "+f"(c[3])
        : "r"(__float_as_uint(a0)), "r"(__float_as_uint(a1)),
          "r"(__float_as_uint(a2)), "r"(__float_as_uint(a3)),
          "r"(__float_as_uint(b0)), "r"(__float_as_uint(b1)));
}

// fp16 k16 mma (GEMMs), fp32 accumulate
__device__ __forceinline__ void mma16(float c[4], uint32_t a0, uint32_t a1,
                                      uint32_t a2, uint32_t a3,
                                      uint32_t b0, uint32_t b1) {
    asm volatile(
        "mma.sync.aligned.m16n8k16.row.col.f32.f16.f16.f32 "
        "{%0,%1,%2,%3}, {%4,%5,%6,%7}, {%8,%9}, {%0,%1,%2,%3};"
        : "+f"(c[0]), "+f"(c[1]), "+f"(c[2]), "+f"(c[3])
        : "r"(a0), "r"(a1), "r"(a2), "r"(a3), "r"(b0), "r"(b1));
}

__device__ __forceinline__ uint32_t smem_u32(const void* p) {
    return (uint32_t)__cvta_generic_to_shared(p);
}
__device__ __forceinline__ void cp_async16(uint32_t dst, const void* src) {
    asm volatile("cp.async.ca.shared.global [%0], [%1], 16;" :: "r"(dst), "l"(src));
}
#define CP_COMMIT() asm volatile("cp.async.commit_group;")
#define CP_WAIT1()  asm volatile("cp.async.wait_group 1;")
#define CP_WAIT0()  asm volatile("cp.async.wait_group 0;")

// ---------------------------------------------------------------------------
// Prepass: fp32 -> fp16 (rna), + mask prescan
// ---------------------------------------------------------------------------
__global__ __launch_bounds__(256) void pre_act_kernel(
    const float* __restrict__ q, const float* __restrict__ k, const float* __restrict__ v)
{
    const int which = blockIdx.y;
    const float* src = (which == 0) ? q : (which == 1) ? k : v;
    __half2* dst = (__half2*)((which == 0) ? g_hq : (which == 1) ? g_hk : g_hv);
    const int n4 = M_ * D_ / 4;
    const int stride = gridDim.x * blockDim.x;
    for (int i = blockIdx.x * blockDim.x + threadIdx.x; i < n4; i += stride) {
        float4 t = ((const float4*)src)[i];
        dst[2 * i] = __floats2half2_rn(t.x, t.y);
        dst[2 * i + 1] = __floats2half2_rn(t.z, t.w);
    }
}

__global__ __launch_bounds__(256) void pre_w_kernel(
    const float* __restrict__ wq, const float* __restrict__ wk,
    const float* __restrict__ wv, const float* __restrict__ wo)
{
    const int which = blockIdx.y;
    const float* src = (which == 0) ? wq : (which == 1) ? wk : (which == 2) ? wv : wo;
    __half2* dst = (__half2*)((which == 0) ? g_hwq : (which == 1) ? g_hwk
                              : (which == 2) ? g_hwv : g_hwo);
    const int n4 = D_ * D_ / 4;
    const int stride = gridDim.x * blockDim.x;
    for (int i = blockIdx.x * blockDim.x + threadIdx.x; i < n4; i += stride) {
        float4 t = ((const float4*)src)[i];
        dst[2 * i] = __floats2half2_rn(t.x, t.y);
        dst[2 * i + 1] = __floats2half2_rn(t.z, t.w);
    }
}

__global__ __launch_bounds__(256) void pre_mask_kernel(const int* __restrict__ mask)
{
    const int qt = blockIdx.x >> 5, kt = blockIdx.x & 31;
    const int tid = threadIdx.x;
    const int r = tid >> 1, h = tid & 1;
    const int* p = mask + (qt * 128 + r) * S_ + kt * 64 + h * 32;
    bool ok = true;
#pragma unroll
    for (int j = 0; j < 8; j++) {
        int4 mv = *(const int4*)(p + j * 4);
        ok &= (mv.x != 0) & (mv.y != 0) & (mv.z != 0) & (mv.w != 0);
    }
    const int all = __syncthreads_and((int)ok);
    if (tid == 0) g_mflag[qt * 32 + kt] = all;
}

// ---------------------------------------------------------------------------
// fp16 tensor-core GEMM: BM=128, BN=256, BK=32 halves, 2-stage double buffer,
// 8 warps as 2m x 4n, warp tile 64x64, m16n8k16 mma. SH=32 halves/row (64B):
// row word-offset 16 => LDS.128 fragment phases hit banks {16g+4tg+0..3} =
// all 32, conflict-free. One LDS.128 per row per iteration covers BOTH k16
// steps via the k-perm (thread tg <- logical cols 8tg..8tg+7, same on A and
// B per step => dot preserved).
// MODE 0: out fp32 [M,D]; 1: head-split fp32 [B,H,S,DK]; 2: transposed
// fp32 [B,H,DK,S].
// ---------------------------------------------------------------------------
#define SH 32
#define ASTG (128 * SH)   // halves
#define BSTG (256 * SH)
#define GEMM_SMEM_BYTES ((2 * ASTG + 2 * BSTG) * 2)   // 49152 B

template <int MODE>
__device__ __forceinline__ void gemm_tc(
    __half* As, __half* Bs,
    const __half* __restrict__ X, const __half* __restrict__ W,
    const float* __restrict__ bias, float* __restrict__ out, float scale)
{
    const int tid = threadIdx.x;
    const int lane = tid & 31, wid = tid >> 5;
    const int g = lane >> 2, tg = lane & 3;
    const int wm = wid >> 2, wn = wid & 3;      // 2m x 4n warps
    const int m0 = blockIdx.y * 128, n0 = blockIdx.x * 256;

    const uint32_t AsU = smem_u32(As), BsU = smem_u32(Bs);
    const int slot = tid & 3;        // 16B slot within a row's 64B chunk
    const int rgrp = tid >> 2;       // 0..63 (base row; rows rgrp + 64*i)

    const __half* xbase = X + (long long)(m0 + rgrp) * D_ + slot * 8;
    const __half* wbase = W + (long long)(n0 + rgrp) * D_ + slot * 8;
    const uint32_t adst = AsU + (uint32_t)(rgrp * SH + slot * 8) * 2;
    const uint32_t bdst = BsU + (uint32_t)(rgrp * SH + slot * 8) * 2;
    const uint32_t sstep = (uint32_t)(64 * SH) * 2;   // 64-row smem step

#define G_ISSUE(s, kb)                                                 \
    do {                                                               \
        const uint32_t ao = (uint32_t)((s) * ASTG) * 2;                \
        const uint32_t bo = (uint32_t)((s) * BSTG) * 2;                \
        _Pragma("unroll")                                              \
        for (int i = 0; i < 2; i++)                                    \
            cp_async16(adst + ao + i * sstep,                          \
                       xbase + (long long)i * 64 * D_ + (kb) * 32);    \
        _Pragma("unroll")                                              \
        for (int i = 0; i < 4; i++)                                    \
            cp_async16(bdst + bo + i * sstep,                          \
                       wbase + (long long)i * 64 * D_ + (kb) * 32);    \
    } while (0)

    float acc[4][8][4];
#pragma unroll
    for (int mt = 0; mt < 4; mt++)
#pragma unroll
        for (int nt = 0; nt < 8; nt++)
#pragma unroll
            for (int i = 0; i < 4; i++) acc[mt][nt][i] = 0.0f;

    G_ISSUE(0, 0);
    CP_COMMIT();

    for (int it = 0; it < 32; it++) {
        CP_WAIT0();
        __syncthreads();
        if (it < 31) {
            G_ISSUE((it + 1) & 1, it + 1);
            CP_COMMIT();
        }

        const __half* Ab = As + (it & 1) * ASTG;
        const __half* Bb = Bs + (it & 1) * BSTG;

        uint4 a0[4], a1[4];
#pragma unroll
        for (int mt = 0; mt < 4; mt++) {
            const int rb = wm * 64 + mt * 16 + g;
            a0[mt] = *(const uint4*)&Ab[rb * SH + 8 * tg];
            a1[mt] = *(const uint4*)&Ab[(rb + 8) * SH + 8 * tg];
        }
#pragma unroll
        for (int nt = 0; nt < 8; nt++) {
            const uint4 b = *(const uint4*)&Bb[(wn * 64 + nt * 8 + g) * SH + 8 * tg];
#pragma unroll
            for (int mt = 0; mt < 4; mt++) {
                mma16(acc[mt][nt], a0[mt].x, a1[mt].x, a0[mt].y, a1[mt].y, b.x, b.y);
                mma16(acc[mt][nt], a0[mt].z, a1[mt].z, a0[mt].w, a1[mt].w, b.z, b.w);
            }
        }
    }
#undef G_ISSUE

#pragma unroll
    for (int mt = 0; mt < 4; mt++) {
        const int r0 = m0 + wm * 64 + mt * 16 + g;
#pragma unroll
        for (int nt = 0; nt < 8; nt++) {
            const int c = n0 + wn * 64 + nt * 8 + tg * 2;
            const float bv0 = bias[c], bv1 = bias[c + 1];
            float v00 = acc[mt][nt][0] + bv0, v01 = acc[mt][nt][1] + bv1;
            float v10 = acc[mt][nt][2] + bv0, v11 = acc[mt][nt][3] + bv1;
            if (MODE >= 1) {
                v00 = to_tf32(v00 * scale); v01 = to_tf32(v01 * scale);
                v10 = to_tf32(v10 * scale); v11 = to_tf32(v11 * scale);
                const int h = c >> 6, dk = c & 63;
                const int bb = r0 >> 11, ss = r0 & 2047;
                if (MODE == 1) {
                    float* o0 = &out[(((bb * H_ + h) * S_) + ss) * DK_ + dk];
                    *(float2*)o0 = make_float2(v00, v01);
                    *(float2*)(o0 + 8 * DK_) = make_float2(v10, v11);
                } else {
                    float* o0 = &out[(((bb * H_ + h) * DK_) + dk) * S_ + ss];
                    o0[0] = v00;
                    o0[8] = v10;
                    o0[S_] = v01;
                    o0[S_ + 8] = v11;
                }
            } else {
                *(float2*)&out[r0 * D_ + c] = make_float2(v00, v01);
                *(float2*)&out[(r0 + 8) * D_ + c] = make_float2(v10, v11);
            }
        }
    }
}

// 0.125 * log2(e)
#define QSCALE 0.1803368801111204f

__global__ __launch_bounds__(256) void qkv_kernel(
    const float* __restrict__ bq, const float* __restrict__ bk,
    const float* __restrict__ bv)
{
    extern __shared__ __align__(16) __half smh[];
    __half* As = smh;
    __half* Bs = smh + 2 * ASTG;
    if (blockIdx.z == 0)      gemm_tc<1>(As, Bs, g_hq, g_hwq, bq, g_q, QSCALE);
    else if (blockIdx.z == 1) gemm_tc<1>(As, Bs, g_hk, g_hwk, bk, g_k, 1.0f);
    else                      gemm_tc<2>(As, Bs, g_hv, g_hwv, bv, g_vT, 1.0f);
}

__global__ __launch_bounds__(256) void oproj_kernel(
    const float* __restrict__ bo, float* __restrict__ out)
{
    extern __shared__ __align__(16) __half smh[];
    __half* As = smh;
    __half* Bs = smh + 2 * ASTG;
    gemm_tc<0>(As, Bs, g_xh, g_hwo, bo, out, 1.0f);
}

// ---------------------------------------------------------------------------
// Flash attention (tf32, unchanged from R14 except fp16 output store):
// Br=256, Q/P in registers, XOR-swizzled stride-64 K/V smem, coalesced
// double-buffered cp.async, base-2 softmax, warp-uniform rescale skip.
// ---------------------------------------------------------------------------
#define ATKV (64 * 64)
#define ATTN_SMEM_BYTES (4 * ATKV * 4)   // 65536 B

__global__ __launch_bounds__(256) void attn_kernel(const int* __restrict__ mask)
{
    extern __shared__ __align__(16) float sm[];
    float* Ks = sm;
    float* Vt = sm + 2 * ATKV;

    const int tid = threadIdx.x;
    const int lane = tid & 31, wid = tid >> 5;
    const int g = lane >> 2, tg = lane & 3;
    const int w32 = wid * 32;
    const int q0 = blockIdx.x * 256;
    const int bh = blockIdx.y;

    const float* Qg = g_q + bh * S_ * DK_;
    const float* Kg = g_k + bh * S_ * DK_;
    const float* Vg = g_vT + bh * DK_ * S_;

    const uint32_t KsU = smem_u32(Ks), VtU = smem_u32(Vt);
    const int slot = tid & 15;
    const int rg = tid >> 4;

#define KV_ISSUE(s, t)                                                            \
    do {                                                                          \
        const uint32_t so = (uint32_t)((s) * ATKV) * 4;                           \
        _Pragma("unroll")                                                         \
        for (int i = 0; i < 4; i++) {                                             \
            const int row = rg + 16 * i;                                          \
            const uint32_t co = (uint32_t)((slot * 4) ^ ((row & 7) * 8)) * 4;     \
            cp_async16(KsU + so + (uint32_t)(row * 64) * 4 + co,                  \
                       Kg + ((t) * 64 + row) * DK_ + slot * 4);                   \
            cp_async16(VtU + so + (uint32_t)(row * 64) * 4 + co,                  \
                       Vg + row * S_ + (t) * 64 + slot * 4);                      \
        }                                                                         \
    } while (0)

    KV_ISSUE(0, 0);
    CP_COMMIT();
    KV_ISSUE(1, 1);
    CP_COMMIT();

    float2 qA[2][8], qB[2][8];
#pragma unroll
    for (int mt = 0; mt < 2; mt++) {
        const float* qlo = Qg + (q0 + w32 + mt * 16 + g) * DK_ + tg * 2;
        const float* qhi = qlo + 8 * DK_;
#pragma unroll
        for (int kk = 0; kk < 8; kk++) {
            qA[mt][kk] = *(const float2*)(qlo + kk * 8);
            qB[mt][kk] = *(const float2*)(qhi + kk * 8);
        }
    }

    float mr[2][2], lr2[2][2];
#pragma unroll
    for (int mt = 0; mt < 2; mt++) {
        mr[mt][0] = -1e30f; mr[mt][1] = -1e30f;
        lr2[mt][0] = 0.0f;  lr2[mt][1] = 0.0f;
    }
    float o[2][8][4];
#pragma unroll
    for (int mt = 0; mt < 2; mt++)
#pragma unroll
        for (int nt = 0; nt < 8; nt++)
#pragma unroll
            for (int i = 0; i < 4; i++) o[mt][nt][i] = 0.0f;

    const int mrow = blockIdx.x * 2;

    for (int kt = 0; kt < 32; kt++) {
        CP_WAIT1();
        __syncthreads();
        const float* Ksb = Ks + (kt & 1) * ATKV;
        const float* Vtb = Vt + (kt & 1) * ATKV;

        float s[2][8][4];
#pragma unroll
        for (int mt = 0; mt < 2; mt++)
#pragma unroll
            for (int nt = 0; nt < 8; nt++)
#pragma unroll
                for (int i = 0; i < 4; i++) s[mt][nt][i] = 0.0f;

#pragma unroll
        for (int kk = 0; kk < 8; kk++) {
            const int fo = 8 * (kk ^ g) + tg * 2;
#pragma unroll
            for (int nt = 0; nt < 8; nt++) {
                const float2 bv = *(const float2*)&Ksb[(nt * 8 + g) * 64 + fo];
                mma8(s[0][nt], qA[0][kk].x, qB[0][kk].x, qA[0][kk].y, qB[0][kk].y,
                     bv.x, bv.y);
                mma8(s[1][nt], qA[1][kk].x, qB[1][kk].x, qA[1][kk].y, qB[1][kk].y,
                     bv.x, bv.y);
            }
        }

        if (!(g_mflag[mrow * 32 + kt] & g_mflag[(mrow + 1) * 32 + kt])) {
            const int k0 = kt * 64;
#pragma unroll
            for (int mt = 0; mt < 2; mt++) {
                const int* mp0 = mask + (q0 + w32 + mt * 16 + g) * S_ + k0 + tg * 2;
                const int* mp1 = mp0 + 8 * S_;
#pragma unroll
                for (int nt = 0; nt < 8; nt++) {
                    const int2 m0v = *(const int2*)(mp0 + nt * 8);
                    const int2 m1v = *(const int2*)(mp1 + nt * 8);
                    if (m0v.x == 0) s[mt][nt][0] = -1e9f;
                    if (m0v.y == 0) s[mt][nt][1] = -1e9f;
                    if (m1v.x == 0) s[mt][nt][2] = -1e9f;
                    if (m1v.y == 0) s[mt][nt][3] = -1e9f;
                }
            }
        }

#pragma unroll
        for (int mt = 0; mt < 2; mt++) {
            float mx0 = -1e30f, mx1 = -1e30f;
#pragma unroll
            for (int nt = 0; nt < 8; nt++) {
                mx0 = fmaxf(mx0, fmaxf(s[mt][nt][0], s[mt][nt][1]));
                mx1 = fmaxf(mx1, fmaxf(s[mt][nt][2], s[mt][nt][3]));
            }
            mx0 = fmaxf(mx0, __shfl_xor_sync(0xffffffffu, mx0, 1));
            mx0 = fmaxf(mx0, __shfl_xor_sync(0xffffffffu, mx0, 2));
            mx1 = fmaxf(mx1, __shfl_xor_sync(0xffffffffu, mx1, 1));
            mx1 = fmaxf(mx1, __shfl_xor_sync(0xffffffffu, mx1, 2));
            const float mn0 = fmaxf(mr[mt][0], mx0);
            const float mn1 = fmaxf(mr[mt][1], mx1);
            const float al0 = exp2f(mr[mt][0] - mn0);
            const float al1 = exp2f(mr[mt][1] - mn1);
            mr[mt][0] = mn0; mr[mt][1] = mn1;

            float sum0 = 0.0f, sum1 = 0.0f;
#pragma unroll
            for (int nt = 0; nt < 8; nt++) {
                const float p0 = exp2f(s[mt][nt][0] - mn0);
                const float p1 = exp2f(s[mt][nt][1] - mn0);
                const float p2 = exp2f(s[mt][nt][2] - mn1);
                const float p3 = exp2f(s[mt][nt][3] - mn1);
                sum0 += p0 + p1;
                sum1 += p2 + p3;
                s[mt][nt][0] = to_tf32(p0);
                s[mt][nt][1] = to_tf32(p1);
                s[mt][nt][2] = to_tf32(p2);
                s[mt][nt][3] = to_tf32(p3);
            }
            if (__any_sync(0xffffffffu, (al0 != 1.0f) || (al1 != 1.0f))) {
#pragma unroll
                for (int nt = 0; nt < 8; nt++) {
                    o[mt][nt][0] *= al0; o[mt][nt][1] *= al0;
                    o[mt][nt][2] *= al1; o[mt][nt][3] *= al1;
                }
            }
            sum0 += __shfl_xor_sync(0xffffffffu, sum0, 1);
            sum0 += __shfl_xor_sync(0xffffffffu, sum0, 2);
            sum1 += __shfl_xor_sync(0xffffffffu, sum1, 1);
            sum1 += __shfl_xor_sync(0xffffffffu, sum1, 2);
            lr2[mt][0] = lr2[mt][0] * al0 + sum0;
            lr2[mt][1] = lr2[mt][1] * al1 + sum1;
        }

#pragma unroll
        for (int kk = 0; kk < 8; kk++) {
            const int fo = 8 * (kk ^ g) + tg * 2;
#pragma unroll
            for (int nt = 0; nt < 8; nt++) {
                const float2 bv = *(const float2*)&Vtb[(nt * 8 + g) * 64 + fo];
                mma8(o[0][nt], s[0][kk][0], s[0][kk][2], s[0][kk][1], s[0][kk][3],
                     bv.x, bv.y);
                mma8(o[1][nt], s[1][kk][0], s[1][kk][2], s[1][kk][1], s[1][kk][3],
                     bv.x, bv.y);
            }
        }

        __syncthreads();
        KV_ISSUE(kt & 1, (kt + 2) & 31);
        CP_COMMIT();
    }
#undef KV_ISSUE

    CP_WAIT0();

    // Normalize and store fp16 (consumed by fp16 oproj)
    const int bb = bh >> 4, h = bh & 15;
#pragma unroll
    for (int mt = 0; mt < 2; mt++) {
        const float inv0 = 1.0f / lr2[mt][0];
        const float inv1 = 1.0f / lr2[mt][1];
        const int r0 = q0 + w32 + mt * 16 + g;
        __half* O0 = &g_xh[(long long)(bb * S_ + r0) * D_ + h * DK_ + tg * 2];
        __half* O1 = O0 + 8 * D_;
#pragma unroll
        for (int nt = 0; nt < 8; nt++) {
            *(__half2*)(O0 + nt * 8) =
                __floats2half2_rn(o[mt][nt][0] * inv0, o[mt][nt][1] * inv0);
            *(__half2*)(O1 + nt * 8) =
                __floats2half2_rn(o[mt][nt][2] * inv1, o[mt][nt][3] * inv1);
        }
    }
}

// ---------------------------------------------------------------------------
extern "C" void kernel_launch(void* const* d_in, const int* in_sizes, int n_in,
                              void* d_out, int out_size)
{
    (void)in_sizes; (void)n_in; (void)out_size;
    const float* q    = (const float*)d_in[0];
    const float* k    = (const float*)d_in[1];
    const float* v    = (const float*)d_in[2];
    const int*   mask = (const int*)d_in[3];
    const float* wq   = (const float*)d_in[4];
    const float* bq   = (const float*)d_in[5];
    const float* wk   = (const float*)d_in[6];
    const float* bk   = (const float*)d_in[7];
    const float* wv   = (const float*)d_in[8];
    const float* bv   = (const float*)d_in[9];
    const float* wo   = (const float*)d_in[10];
    const float* bo   = (const float*)d_in[11];
    float* out = (float*)d_out;

    static bool attrs_set = false;
    if (!attrs_set) {
        cudaFuncSetAttribute(qkv_kernel, cudaFuncAttributeMaxDynamicSharedMemorySize,
                             GEMM_SMEM_BYTES);
        cudaFuncSetAttribute(oproj_kernel, cudaFuncAttributeMaxDynamicSharedMemorySize,
                             GEMM_SMEM_BYTES);
        cudaFuncSetAttribute(attn_kernel, cudaFuncAttributeMaxDynamicSharedMemorySize,
                             ATTN_SMEM_BYTES);
        attrs_set = true;
    }

    // Prepass (3 launches so qkv stays the 4th = ncu capture slot)
    dim3 ga(512, 3);
    pre_act_kernel<<<ga, 256>>>(q, k, v);
    dim3 gw(256, 4);
    pre_w_kernel<<<gw, 256>>>(wq, wk, wv, wo);
    pre_mask_kernel<<<512, 256>>>(mask);

    // QKV projections (fp16 operands; V writes g_vT transposed)
    dim3 gqkv(D_ / 256, M_ / 128, 3);
    qkv_kernel<<<gqkv, 256, GEMM_SMEM_BYTES>>>(bq, bk, bv);

    // Attention (tf32)
    dim3 gattn(S_ / 256, B_ * H_);
    attn_kernel<<<gattn, 256, ATTN_SMEM_BYTES>>>(mask);

    // Output projection (fp16 operands)
    dim3 gop(D_ / 256, M_ / 128);
    oproj_kernel<<<gop, 256, GEMM_SMEM_BYTES>>>(bo, out);
}

// round 17
// speedup vs baseline: 1.8689x; 1.2801x over previous
#include <cuda_runtime.h>
#include <cuda_fp16.h>
#include <cstdint>
#include <cstring>

#define B_ 4
#define S_ 2048
#define D_ 1024
#define H_ 16
#define DK_ 64
#define M_ (B_ * S_)   // 8192

// fp16 tensors (GEMM + attention operands)
__device__ __half g_q16[M_ * D_];   // [B,H,S,DK] q proj, pre-scaled 0.125*log2e
__device__ __half g_k16[M_ * D_];   // [B,H,S,DK]
__device__ __half g_vT16[M_ * D_];  // [B,H,DK,S]
__device__ __half g_hq[M_ * D_];    // fp16 copies of raw inputs
__device__ __half g_hk[M_ * D_];
__device__ __half g_hv[M_ * D_];
__device__ __half g_hwq[D_ * D_];
__device__ __half g_hwk[D_ * D_];
__device__ __half g_hwv[D_ * D_];
__device__ __half g_hwo[D_ * D_];
__device__ __half g_xh[M_ * D_];    // attention out (oproj input)
__device__ int    g_mflag[16 * 32];

// fp16 k16 mma, fp32 accumulate
__device__ __forceinline__ void mma16(float c[4], uint32_t a0, uint32_t a1,
                                      uint32_t a2, uint32_t a3,
                                      uint32_t b0, uint32_t b1) {
    asm volatile(
        "mma.sync.aligned.m16n8k16.row.col.f32.f16.f16.f32 "
        "{%0,%1,%2,%3}, {%4,%5,%6,%7}, {%8,%9}, {%0,%1,%2,%3};"
        : "+f"(c[0]), "+f"(c[1]), "+f"(c[2]), "+f"(c[3])
        : "r"(a0), "r"(a1), "r"(a2), "r"(a3), "r"(b0), "r"(b1));
}

__device__ __forceinline__ uint32_t h2u(__half2 h) {
    uint32_t u;
    memcpy(&u, &h, 4);
    return u;
}

__device__ __forceinline__ uint32_t smem_u32(const void* p) {
    return (uint32_t)__cvta_generic_to_shared(p);
}
__device__ __forceinline__ void cp_async16(uint32_t dst, const void* src) {
    asm volatile("cp.async.ca.shared.global [%0], [%1], 16;" :: "r"(dst), "l"(src));
}
#define CP_COMMIT() asm volatile("cp.async.commit_group;")
#define CP_WAIT1()  asm volatile("cp.async.wait_group 1;")
#define CP_WAIT0()  asm volatile("cp.async.wait_group 0;")

// ---------------------------------------------------------------------------
// Prepass: fp32 -> fp16 (rn) for activations+weights (one kernel), + mask scan
// ---------------------------------------------------------------------------
__global__ __launch_bounds__(256) void pre_all_kernel(
    const float* __restrict__ q, const float* __restrict__ k, const float* __restrict__ v,
    const float* __restrict__ wq, const float* __restrict__ wk,
    const float* __restrict__ wv, const float* __restrict__ wo)
{
    const int which = blockIdx.y;
    const float* src;
    __half2* dst;
    int n4;
    if (which < 3) {
        n4 = M_ * D_ / 4;
        src = (which == 0) ? q : (which == 1) ? k : v;
        dst = (__half2*)((which == 0) ? g_hq : (which == 1) ? g_hk : g_hv);
    } else {
        n4 = D_ * D_ / 4;
        src = (which == 3) ? wq : (which == 4) ? wk : (which == 5) ? wv : wo;
        dst = (__half2*)((which == 3) ? g_hwq : (which == 4) ? g_hwk
                         : (which == 5) ? g_hwv : g_hwo);
    }
    const int stride = gridDim.x * blockDim.x;
    for (int i = blockIdx.x * blockDim.x + threadIdx.x; i < n4; i += stride) {
        float4 t = ((const float4*)src)[i];
        dst[2 * i] = __floats2half2_rn(t.x, t.y);
        dst[2 * i + 1] = __floats2half2_rn(t.z, t.w);
    }
}

__global__ __launch_bounds__(256) void pre_mask_kernel(const int* __restrict__ mask)
{
    const int qt = blockIdx.x >> 5, kt = blockIdx.x & 31;
    const int tid = threadIdx.x;
    const int r = tid >> 1, h = tid & 1;
    const int* p = mask + (qt * 128 + r) * S_ + kt * 64 + h * 32;
    bool ok = true;
#pragma unroll
    for (int j = 0; j < 8; j++) {
        int4 mv = *(const int4*)(p + j * 4);
        ok &= (mv.x != 0) & (mv.y != 0) & (mv.z != 0) & (mv.w != 0);
    }
    const int all = __syncthreads_and((int)ok);
    if (tid == 0) g_mflag[qt * 32 + kt] = all;
}

// ---------------------------------------------------------------------------
// fp16 tensor-core GEMM (R15 structure): BM=128, BN=256, BK=32 halves,
// 2-stage, 8 warps 2m x 4n, warp tile 64x64, SH=32 halves/row.
// MODE 0: out fp32 [M,D]; 1: fp16 head-split [B,H,S,DK]; 2: fp16 transposed
// [B,H,DK,S].
// ---------------------------------------------------------------------------
#define SH 32
#define ASTG (128 * SH)
#define BSTG (256 * SH)
#define GEMM_SMEM_BYTES ((2 * ASTG + 2 * BSTG) * 2)   // 49152 B

template <int MODE>
__device__ __forceinline__ void gemm_tc(
    __half* As, __half* Bs,
    const __half* __restrict__ X, const __half* __restrict__ W,
    const float* __restrict__ bias, void* __restrict__ outv, float scale)
{
    const int tid = threadIdx.x;
    const int lane = tid & 31, wid = tid >> 5;
    const int g = lane >> 2, tg = lane & 3;
    const int wm = wid >> 2, wn = wid & 3;
    const int m0 = blockIdx.y * 128, n0 = blockIdx.x * 256;

    const uint32_t AsU = smem_u32(As), BsU = smem_u32(Bs);
    const int slot = tid & 3;
    const int rgrp = tid >> 2;

    const __half* xbase = X + (long long)(m0 + rgrp) * D_ + slot * 8;
    const __half* wbase = W + (long long)(n0 + rgrp) * D_ + slot * 8;
    const uint32_t adst = AsU + (uint32_t)(rgrp * SH + slot * 8) * 2;
    const uint32_t bdst = BsU + (uint32_t)(rgrp * SH + slot * 8) * 2;
    const uint32_t sstep = (uint32_t)(64 * SH) * 2;

#define G_ISSUE(s, kb)                                                 \
    do {                                                               \
        const uint32_t ao = (uint32_t)((s) * ASTG) * 2;                \
        const uint32_t bo = (uint32_t)((s) * BSTG) * 2;                \
        _Pragma("unroll")                                              \
        for (int i = 0; i < 2; i++)                                    \
            cp_async16(adst + ao + i * sstep,                          \
                       xbase + (long long)i * 64 * D_ + (kb) * 32);    \
        _Pragma("unroll")                                              \
        for (int i = 0; i < 4; i++)                                    \
            cp_async16(bdst + bo + i * sstep,                          \
                       wbase + (long long)i * 64 * D_ + (kb) * 32);    \
    } while (0)

    float acc[4][8][4];
#pragma unroll
    for (int mt = 0; mt < 4; mt++)
#pragma unroll
        for (int nt = 0; nt < 8; nt++)
#pragma unroll
            for (int i = 0; i < 4; i++) acc[mt][nt][i] = 0.0f;

    G_ISSUE(0, 0);
    CP_COMMIT();

    for (int it = 0; it < 32; it++) {
        CP_WAIT0();
        __syncthreads();
        if (it < 31) {
            G_ISSUE((it + 1) & 1, it + 1);
            CP_COMMIT();
        }

        const __half* Ab = As + (it & 1) * ASTG;
        const __half* Bb = Bs + (it & 1) * BSTG;

        uint4 a0[4], a1[4];
#pragma unroll
        for (int mt = 0; mt < 4; mt++) {
            const int rb = wm * 64 + mt * 16 + g;
            a0[mt] = *(const uint4*)&Ab[rb * SH + 8 * tg];
            a1[mt] = *(const uint4*)&Ab[(rb + 8) * SH + 8 * tg];
        }
#pragma unroll
        for (int nt = 0; nt < 8; nt++) {
            const uint4 b = *(const uint4*)&Bb[(wn * 64 + nt * 8 + g) * SH + 8 * tg];
#pragma unroll
            for (int mt = 0; mt < 4; mt++) {
                mma16(acc[mt][nt], a0[mt].x, a1[mt].x, a0[mt].y, a1[mt].y, b.x, b.y);
                mma16(acc[mt][nt], a0[mt].z, a1[mt].z, a0[mt].w, a1[mt].w, b.z, b.w);
            }
        }
    }
#undef G_ISSUE

#pragma unroll
    for (int mt = 0; mt < 4; mt++) {
        const int r0 = m0 + wm * 64 + mt * 16 + g;
#pragma unroll
        for (int nt = 0; nt < 8; nt++) {
            const int c = n0 + wn * 64 + nt * 8 + tg * 2;
            const float bv0 = bias[c], bv1 = bias[c + 1];
            float v00 = acc[mt][nt][0] + bv0, v01 = acc[mt][nt][1] + bv1;
            float v10 = acc[mt][nt][2] + bv0, v11 = acc[mt][nt][3] + bv1;
            if (MODE >= 1) {
                v00 *= scale; v01 *= scale; v10 *= scale; v11 *= scale;
                const int h = c >> 6, dk = c & 63;
                const int bb = r0 >> 11, ss = r0 & 2047;
                __half* out = (__half*)outv;
                if (MODE == 1) {
                    __half* o0 = &out[(long long)(((bb * H_ + h) * S_) + ss) * DK_ + dk];
                    *(__half2*)o0 = __floats2half2_rn(v00, v01);
                    *(__half2*)(o0 + 8 * DK_) = __floats2half2_rn(v10, v11);
                } else {
                    __half* o0 = &out[(long long)(((bb * H_ + h) * DK_) + dk) * S_ + ss];
                    o0[0] = __float2half_rn(v00);
                    o0[8] = __float2half_rn(v10);
                    o0[S_] = __float2half_rn(v01);
                    o0[S_ + 8] = __float2half_rn(v11);
                }
            } else {
                float* out = (float*)outv;
                *(float2*)&out[(long long)r0 * D_ + c] = make_float2(v00, v01);
                *(float2*)&out[(long long)(r0 + 8) * D_ + c] = make_float2(v10, v11);
            }
        }
    }
}

// 0.125 * log2(e)
#define QSCALE 0.1803368801111204f

__global__ __launch_bounds__(256) void qkv_kernel(
    const float* __restrict__ bq, const float* __restrict__ bk,
    const float* __restrict__ bv)
{
    extern __shared__ __align__(16) __half smh[];
    __half* As = smh;
    __half* Bs = smh + 2 * ASTG;
    if (blockIdx.z == 0)      gemm_tc<1>(As, Bs, g_hq, g_hwq, bq, g_q16, QSCALE);
    else if (blockIdx.z == 1) gemm_tc<1>(As, Bs, g_hk, g_hwk, bk, g_k16, 1.0f);
    else                      gemm_tc<2>(As, Bs, g_hv, g_hwv, bv, g_vT16, 1.0f);
}

__global__ __launch_bounds__(256) void oproj_kernel(
    const float* __restrict__ bo, float* __restrict__ out)
{
    extern __shared__ __align__(16) __half smh[];
    __half* As = smh;
    __half* Bs = smh + 2 * ASTG;
    gemm_tc<0>(As, Bs, g_xh, g_hwo, bo, out, 1.0f);
}

// ---------------------------------------------------------------------------
// fp16 flash attention: Br=256, warp owns 32 q-rows, Q/P in registers,
// m16n8k16 mma, padded fp16 K (stride 80) / V^T (stride 72) smem,
// coalesced double-buffered cp.async, base-2 softmax, rescale skip.
// ---------------------------------------------------------------------------
#define SHK 80
#define SHV 72
#define KSTG (64 * SHK)
#define VSTG (64 * SHV)
#define ATTN_SMEM_BYTES ((2 * KSTG + 2 * VSTG) * 2)   // 38912 B

__global__ __launch_bounds__(256) void attn_kernel(const int* __restrict__ mask)
{
    extern __shared__ __align__(16) __half smh[];
    __half* Ks = smh;
    __half* Vt = smh + 2 * KSTG;

    const int tid = threadIdx.x;
    const int lane = tid & 31, wid = tid >> 5;
    const int g = lane >> 2, tg = lane & 3;
    const int w32 = wid * 32;
    const int q0 = blockIdx.x * 256;
    const int bh = blockIdx.y;

    const __half* Qg = g_q16 + (long long)bh * S_ * DK_;
    const __half* Kg = g_k16 + (long long)bh * S_ * DK_;
    const __half* Vg = g_vT16 + (long long)bh * DK_ * S_;

    const uint32_t KsU = smem_u32(Ks), VtU = smem_u32(Vt);

#define KV_ISSUE(s, t)                                                          \
    do {                                                                        \
        _Pragma("unroll")                                                       \
        for (int i = 0; i < 2; i++) {                                           \
            const int gi = tid + i * 256;                                       \
            const int row = gi >> 3, gr = gi & 7;                               \
            cp_async16(KsU + (uint32_t)((s) * KSTG + row * SHK + gr * 8) * 2,   \
                       Kg + ((t) * 64 + row) * DK_ + gr * 8);                   \
            cp_async16(VtU + (uint32_t)((s) * VSTG + row * SHV + gr * 8) * 2,   \
                       Vg + (long long)row * S_ + (t) * 64 + gr * 8);           \
        }                                                                       \
    } while (0)

    KV_ISSUE(0, 0);
    CP_COMMIT();
    KV_ISSUE(1, 1);
    CP_COMMIT();

    // Q fragments (fp16 packed) in registers: [mt][j][row g / g+8]
    uint2 qf[2][4][2];
#pragma unroll
    for (int mt = 0; mt < 2; mt++) {
        const __half* qlo = Qg + (long long)(q0 + w32 + mt * 16 + g) * DK_;
        const __half* qhi = qlo + 8 * DK_;
#pragma unroll
        for (int j = 0; j < 4; j++) {
            qf[mt][j][0] = *(const uint2*)(qlo + 16 * j + 4 * tg);
            qf[mt][j][1] = *(const uint2*)(qhi + 16 * j + 4 * tg);
        }
    }

    float mr[2][2], lr2[2][2];
#pragma unroll
    for (int mt = 0; mt < 2; mt++) {
        mr[mt][0] = -1e30f; mr[mt][1] = -1e30f;
        lr2[mt][0] = 0.0f;  lr2[mt][1] = 0.0f;
    }
    float o[2][8][4];
#pragma unroll
    for (int mt = 0; mt < 2; mt++)
#pragma unroll
        for (int nt = 0; nt < 8; nt++)
#pragma unroll
            for (int i = 0; i < 4; i++) o[mt][nt][i] = 0.0f;

    const int mrow = blockIdx.x * 2;

    for (int kt = 0; kt < 32; kt++) {
        CP_WAIT1();
        __syncthreads();
        const __half* Ksb = Ks + (kt & 1) * KSTG;
        const __half* Vtb = Vt + (kt & 1) * VSTG;

        // S = Q @ K^T (warp: 32x64), fp16 mma
        float s[2][8][4];
#pragma unroll
        for (int mt = 0; mt < 2; mt++)
#pragma unroll
            for (int nt = 0; nt < 8; nt++)
#pragma unroll
                for (int i = 0; i < 4; i++) s[mt][nt][i] = 0.0f;

#pragma unroll
        for (int j = 0; j < 4; j++) {
#pragma unroll
            for (int nt = 0; nt < 8; nt++) {
                const uint2 b = *(const uint2*)&Ksb[(nt * 8 + g) * SHK + 16 * j + 4 * tg];
                mma16(s[0][nt], qf[0][j][0].x, qf[0][j][1].x,
                      qf[0][j][0].y, qf[0][j][1].y, b.x, b.y);
                mma16(s[1][nt], qf[1][j][0].x, qf[1][j][1].x,
                      qf[1][j][0].y, qf[1][j][1].y, b.x, b.y);
            }
        }

        if (!(g_mflag[mrow * 32 + kt] & g_mflag[(mrow + 1) * 32 + kt])) {
            const int k0 = kt * 64;
#pragma unroll
            for (int mt = 0; mt < 2; mt++) {
                const int* mp0 = mask + (q0 + w32 + mt * 16 + g) * S_ + k0 + tg * 2;
                const int* mp1 = mp0 + 8 * S_;
#pragma unroll
                for (int nt = 0; nt < 8; nt++) {
                    const int2 m0v = *(const int2*)(mp0 + nt * 8);
                    const int2 m1v = *(const int2*)(mp1 + nt * 8);
                    if (m0v.x == 0) s[mt][nt][0] = -1e9f;
                    if (m0v.y == 0) s[mt][nt][1] = -1e9f;
                    if (m1v.x == 0) s[mt][nt][2] = -1e9f;
                    if (m1v.y == 0) s[mt][nt][3] = -1e9f;
                }
            }
        }

        // Online softmax (base 2)
#pragma unroll
        for (int mt = 0; mt < 2; mt++) {
            float mx0 = -1e30f, mx1 = -1e30f;
#pragma unroll
            for (int nt = 0; nt < 8; nt++) {
                mx0 = fmaxf(mx0, fmaxf(s[mt][nt][0], s[mt][nt][1]));
                mx1 = fmaxf(mx1, fmaxf(s[mt][nt][2], s[mt][nt][3]));
            }
            mx0 = fmaxf(mx0, __shfl_xor_sync(0xffffffffu, mx0, 1));
            mx0 = fmaxf(mx0, __shfl_xor_sync(0xffffffffu, mx0, 2));
            mx1 = fmaxf(mx1, __shfl_xor_sync(0xffffffffu, mx1, 1));
            mx1 = fmaxf(mx1, __shfl_xor_sync(0xffffffffu, mx1, 2));
            const float mn0 = fmaxf(mr[mt][0], mx0);
            const float mn1 = fmaxf(mr[mt][1], mx1);
            const float al0 = exp2f(mr[mt][0] - mn0);
            const float al1 = exp2f(mr[mt][1] - mn1);
            mr[mt][0] = mn0; mr[mt][1] = mn1;

            float sum0 = 0.0f, sum1 = 0.0f;
#pragma unroll
            for (int nt = 0; nt < 8; nt++) {
                s[mt][nt][0] = exp2f(s[mt][nt][0] - mn0);
                s[mt][nt][1] = exp2f(s[mt][nt][1] - mn0);
                s[mt][nt][2] = exp2f(s[mt][nt][2] - mn1);
                s[mt][nt][3] = exp2f(s[mt][nt][3] - mn1);
                sum0 += s[mt][nt][0] + s[mt][nt][1];
                sum1 += s[mt][nt][2] + s[mt][nt][3];
            }
            if (__any_sync(0xffffffffu, (al0 != 1.0f) || (al1 != 1.0f))) {
#pragma unroll
                for (int nt = 0; nt < 8; nt++) {
                    o[mt][nt][0] *= al0; o[mt][nt][1] *= al0;
                    o[mt][nt][2] *= al1; o[mt][nt][3] *= al1;
                }
            }
            sum0 += __shfl_xor_sync(0xffffffffu, sum0, 1);
            sum0 += __shfl_xor_sync(0xffffffffu, sum0, 2);
            sum1 += __shfl_xor_sync(0xffffffffu, sum1, 1);
            sum1 += __shfl_xor_sync(0xffffffffu, sum1, 2);
            lr2[mt][0] = lr2[mt][0] * al0 + sum0;
            lr2[mt][1] = lr2[mt][1] * al1 + sum1;
        }

        // O += P @ V (P packed to fp16 A-frags in registers; V via 2x LDS.32)
#pragma unroll
        for (int j = 0; j < 4; j++) {
            uint32_t pa[2][4];
#pragma unroll
            for (int mt = 0; mt < 2; mt++) {
                pa[mt][0] = h2u(__floats2half2_rn(s[mt][2 * j][0], s[mt][2 * j][1]));
                pa[mt][1] = h2u(__floats2half2_rn(s[mt][2 * j][2], s[mt][2 * j][3]));
                pa[mt][2] = h2u(__floats2half2_rn(s[mt][2 * j + 1][0], s[mt][2 * j + 1][1]));
                pa[mt][3] = h2u(__floats2half2_rn(s[mt][2 * j + 1][2], s[mt][2 * j + 1][3]));
            }
#pragma unroll
            for (int nt = 0; nt < 8; nt++) {
                const __half* vrow = &Vtb[(nt * 8 + g) * SHV + 16 * j];
                const uint32_t b0 = *(const uint32_t*)(vrow + 2 * tg);
                const uint32_t b1 = *(const uint32_t*)(vrow + 8 + 2 * tg);
                mma16(o[0][nt], pa[0][0], pa[0][1], pa[0][2], pa[0][3], b0, b1);
                mma16(o[1][nt], pa[1][0], pa[1][1], pa[1][2], pa[1][3], b0, b1);
            }
        }

        __syncthreads();
        KV_ISSUE(kt & 1, (kt + 2) & 31);
        CP_COMMIT();
    }
#undef KV_ISSUE

    CP_WAIT0();

    // Normalize and store fp16 (oproj input)
    const int bb = bh >> 4, h = bh & 15;
#pragma unroll
    for (int mt = 0; mt < 2; mt++) {
        const float inv0 = 1.0f / lr2[mt][0];
        const float inv1 = 1.0f / lr2[mt][1];
        const int r0 = q0 + w32 + mt * 16 + g;
        __half* O0 = &g_xh[(long long)(bb * S_ + r0) * D_ + h * DK_ + tg * 2];
        __half* O1 = O0 + 8 * D_;
#pragma unroll
        for (int nt = 0; nt < 8; nt++) {
            *(__half2*)(O0 + nt * 8) =
                __floats2half2_rn(o[mt][nt][0] * inv0, o[mt][nt][1] * inv0);
            *(__half2*)(O1 + nt * 8) =
                __floats2half2_rn(o[mt][nt][2] * inv1, o[mt][nt][3] * inv1);
        }
    }
}

// ---------------------------------------------------------------------------
extern "C" void kernel_launch(void* const* d_in, const int* in_sizes, int n_in,
                              void* d_out, int out_size)
{
    (void)in_sizes; (void)n_in; (void)out_size;
    const float* q    = (const float*)d_in[0];
    const float* k    = (const float*)d_in[1];
    const float* v    = (const float*)d_in[2];
    const int*   mask = (const int*)d_in[3];
    const float* wq   = (const float*)d_in[4];
    const float* bq   = (const float*)d_in[5];
    const float* wk   = (const float*)d_in[6];
    const float* bk   = (const float*)d_in[7];
    const float* wv   = (const float*)d_in[8];
    const float* bv   = (const float*)d_in[9];
    const float* wo   = (const float*)d_in[10];
    const float* bo   = (const float*)d_in[11];
    float* out = (float*)d_out;

    static bool attrs_set = false;
    if (!attrs_set) {
        cudaFuncSetAttribute(qkv_kernel, cudaFuncAttributeMaxDynamicSharedMemorySize,
                             GEMM_SMEM_BYTES);
        cudaFuncSetAttribute(oproj_kernel, cudaFuncAttributeMaxDynamicSharedMemorySize,
                             GEMM_SMEM_BYTES);
        cudaFuncSetAttribute(attn_kernel, cudaFuncAttributeMaxDynamicSharedMemorySize,
                             ATTN_SMEM_BYTES);
        attrs_set = true;
    }

    // Prepass (2 launches => attn is the 4th = ncu capture slot)
    dim3 gpre(512, 7);
    pre_all_kernel<<<gpre, 256>>>(q, k, v, wq, wk, wv, wo);
    pre_mask_kernel<<<512, 256>>>(mask);

    // QKV projections (fp16 in/out; V written transposed)
    dim3 gqkv(D_ / 256, M_ / 128, 3);
    qkv_kernel<<<gqkv, 256, GEMM_SMEM_BYTES>>>(bq, bk, bv);

    // Attention (fp16 mma)
    dim3 gattn(S_ / 256, B_ * H_);
    attn_kernel<<<gattn, 256, ATTN_SMEM_BYTES>>>(mask);

    // Output projection
    dim3 gop(D_ / 256, M_ / 128);
    oproj_kernel<<<gop, 256, GEMM_SMEM_BYTES>>>(bo, out);
}